// round 1
// baseline (speedup 1.0000x reference)
#include <cuda_runtime.h>

#define NN 50000
#define EE 800000
#define PP 12
#define FF 8
#define HIDD 64
#define OUTD 96

// ---------------- scratch (device globals; no allocation) ----------------
__device__ float  g_deg[NN];
__device__ float  g_dinv[NN];
__device__ float4 g_xT[PP * NN * 2];     // [p][n][half] as float4 (8 floats/node/period)
__device__ float4 g_Xagg[PP * NN * 2];   // aggregated (A_hat @ x_p), same layout
__device__ float  g_H[NN * HIDD];        // relu(H_accum)
__device__ float  g_sums[HIDD];
__device__ float  g_sumsq[HIDD];
__device__ float  g_Az[FF * HIDD], g_Ah[FF * HIDD];
__device__ float  g_cz[HIDD], g_ch[HIDD];
__device__ float  g_probs[PP];
__device__ float  g_Wc[HIDD * OUTD], g_bc[OUTD];
__device__ float  g_Weff[HIDD * OUTD], g_beff[OUTD];

// ---------------- tiny precompute: fold all the small linear algebra ------
__global__ void k_pre1(const float* __restrict__ att,
                       const float* __restrict__ conv_w, const float* __restrict__ conv_b,
                       const float* __restrict__ lin_w,  const float* __restrict__ lin_b,
                       const float* __restrict__ W1, const float* __restrict__ b1,
                       const float* __restrict__ W2, const float* __restrict__ b2,
                       const float* __restrict__ W3, const float* __restrict__ b3,
                       const float* __restrict__ W4, const float* __restrict__ b4,
                       const float* __restrict__ W5, const float* __restrict__ b5) {
    int tid = threadIdx.x;
    __shared__ float sT1[64 * 32];
    __shared__ float sT2[64 * 16];
    __shared__ float sT3[64 * 8];
    __shared__ float sb[56];   // [0:32) bb2, [32:48) bb3, [48:56) bb4

    if (tid == 0) {
        float m = -1e30f;
        for (int i = 0; i < PP; i++) m = fmaxf(m, att[i]);
        float e[PP], s = 0.f;
        for (int i = 0; i < PP; i++) { e[i] = __expf(att[i] - m); s += e[i]; }
        for (int i = 0; i < PP; i++) g_probs[i] = e[i] / s;
    }

    // Az = conv_w[0] @ lin_w[0][:64],  Ah = conv_w[2] @ lin_w[2][:64]   (8x64 each)
    for (int idx = tid; idx < FF * HIDD; idx += blockDim.x) {
        int i = idx >> 6, j = idx & 63;
        float az = 0.f, ah = 0.f;
        for (int k = 0; k < HIDD; k++) {
            az += conv_w[0 * 512 + i * 64 + k] * lin_w[0 * 8192 + k * 64 + j];
            ah += conv_w[2 * 512 + i * 64 + k] * lin_w[2 * 8192 + k * 64 + j];
        }
        g_Az[idx] = az; g_Ah[idx] = ah;
    }
    // cz = conv_b[0]@Wz + lin_b[0],  ch = conv_b[2]@Wh + lin_b[2]; also zero BN stats
    for (int j = tid; j < HIDD; j += blockDim.x) {
        float cz = lin_b[0 * 64 + j], ch = lin_b[2 * 64 + j];
        for (int k = 0; k < HIDD; k++) {
            cz += conv_b[0 * 64 + k] * lin_w[0 * 8192 + k * 64 + j];
            ch += conv_b[2 * 64 + k] * lin_w[2 * 8192 + k * 64 + j];
        }
        g_cz[j] = cz; g_ch[j] = ch;
        g_sums[j] = 0.f; g_sumsq[j] = 0.f;
    }

    // Wc = W1@W2@W3@W4@W5 (64x96), bc = folded bias
    for (int idx = tid; idx < 64 * 32; idx += blockDim.x) {
        int i = idx >> 5, j = idx & 31; float s = 0.f;
        for (int k = 0; k < 64; k++) s += W1[i * 64 + k] * W2[k * 32 + j];
        sT1[idx] = s;
    }
    if (tid < 32) { float s = b2[tid]; for (int k = 0; k < 64; k++) s += b1[k] * W2[k * 32 + tid]; sb[tid] = s; }
    __syncthreads();
    for (int idx = tid; idx < 64 * 16; idx += blockDim.x) {
        int i = idx >> 4, j = idx & 15; float s = 0.f;
        for (int k = 0; k < 32; k++) s += sT1[i * 32 + k] * W3[k * 16 + j];
        sT2[idx] = s;
    }
    if (tid < 16) { float s = b3[tid]; for (int k = 0; k < 32; k++) s += sb[k] * W3[k * 16 + tid]; sb[32 + tid] = s; }
    __syncthreads();
    for (int idx = tid; idx < 64 * 8; idx += blockDim.x) {
        int i = idx >> 3, j = idx & 7; float s = 0.f;
        for (int k = 0; k < 16; k++) s += sT2[i * 16 + k] * W4[k * 8 + j];
        sT3[idx] = s;
    }
    if (tid < 8) { float s = b4[tid]; for (int k = 0; k < 16; k++) s += sb[32 + k] * W4[k * 8 + tid]; sb[48 + tid] = s; }
    __syncthreads();
    for (int idx = tid; idx < 64 * 96; idx += blockDim.x) {
        int i = idx / 96, j = idx - i * 96; float s = 0.f;
        for (int k = 0; k < 8; k++) s += sT3[i * 8 + k] * W5[k * 96 + j];
        g_Wc[idx] = s;
    }
    for (int j = tid; j < 96; j += blockDim.x) {
        float s = b5[j];
        for (int k = 0; k < 8; k++) s += sb[48 + k] * W5[k * 96 + j];
        g_bc[j] = s;
    }
}

// ---------------- degree / normalization ---------------------------------
__global__ void k_deg_init() {
    int n = blockIdx.x * blockDim.x + threadIdx.x;
    if (n < NN) g_deg[n] = 1.0f;     // self-loop weight 1
}
__global__ void k_deg(const int* __restrict__ ei, const float* __restrict__ ew) {
    int e = blockIdx.x * blockDim.x + threadIdx.x;
    if (e < EE) atomicAdd(&g_deg[ei[EE + e]], ew[e]);
}
__global__ void k_dinv() {
    int n = blockIdx.x * blockDim.x + threadIdx.x;
    if (n < NN) g_dinv[n] = rsqrtf(g_deg[n]);
}

// ---------------- transpose x to [p][n][f] + self-loop init of Xagg -------
__global__ void k_prepx(const float* __restrict__ x) {
    int t = blockIdx.x * blockDim.x + threadIdx.x;
    if (t >= PP * NN * 2) return;
    int p = t / (NN * 2);
    int r = t - p * NN * 2;
    int n = r >> 1;
    int h = r & 1;
    float d = g_dinv[n];
    float sn = d * d;
    int f0 = h * 4;
    const float* xb = x + n * 96 + p;
    float4 v;
    v.x = xb[(f0 + 0) * 12];
    v.y = xb[(f0 + 1) * 12];
    v.z = xb[(f0 + 2) * 12];
    v.w = xb[(f0 + 3) * 12];
    g_xT[t] = v;
    float4 a; a.x = sn * v.x; a.y = sn * v.y; a.z = sn * v.z; a.w = sn * v.w;
    g_Xagg[t] = a;
}

// ---------------- edge scatter: Xagg[col] += enorm * xT[row] --------------
__global__ void k_scatter(const int* __restrict__ ei, const float* __restrict__ ew) {
    int gtid = blockIdx.x * blockDim.x + threadIdx.x;
    int e = gtid >> 5;
    int lane = threadIdx.x & 31;
    if (e >= EE) return;
    int row = ei[e];
    int col = ei[EE + e];
    float c = g_dinv[row] * ew[e] * g_dinv[col];
    if (lane < 24) {                       // 24 lanes x float4 = 96 floats
        int p = lane >> 1, h = lane & 1;
        float4 v = g_xT[(p * NN + row) * 2 + h];
        float4 a; a.x = c * v.x; a.y = c * v.y; a.z = c * v.z; a.w = c * v.w;
        float4* dst = &g_Xagg[(p * NN + col) * 2 + h];
        asm volatile("red.global.add.v4.f32 [%0], {%1, %2, %3, %4};"
                     :: "l"(dst), "f"(a.x), "f"(a.y), "f"(a.z), "f"(a.w)
                     : "memory");
    }
}

// ---------------- per-node collapsed GRU over periods + BN stats ----------
__global__ void k_H() {
    __shared__ float bsum[64], bsq[64];
    if (threadIdx.x < 64) { bsum[threadIdx.x] = 0.f; bsq[threadIdx.x] = 0.f; }
    __syncthreads();

    int n = (blockIdx.x * blockDim.x + threadIdx.x) >> 5;
    int lane = threadIdx.x & 31;
    float hx = 0.f, hy = 0.f;
    if (n < NN) {
        float2 az[8], ah[8];
        #pragma unroll
        for (int i = 0; i < 8; i++) {
            az[i] = *(const float2*)&g_Az[i * 64 + 2 * lane];
            ah[i] = *(const float2*)&g_Ah[i * 64 + 2 * lane];
        }
        float2 cz = *(const float2*)&g_cz[2 * lane];
        float2 ch = *(const float2*)&g_ch[2 * lane];
        #pragma unroll
        for (int p = 0; p < PP; p++) {
            float4 u0 = g_Xagg[(p * NN + n) * 2];
            float4 u1 = g_Xagg[(p * NN + n) * 2 + 1];
            float u[8] = {u0.x, u0.y, u0.z, u0.w, u1.x, u1.y, u1.z, u1.w};
            float ax = cz.x, ay = cz.y, bx = ch.x, by = ch.y;
            #pragma unroll
            for (int i = 0; i < 8; i++) {
                ax += u[i] * az[i].x;  ay += u[i] * az[i].y;
                bx += u[i] * ah[i].x;  by += u[i] * ah[i].y;
            }
            // (1 - sigmoid(a)) = 1/(1+e^a);  tanh(b) = 1 - 2/(e^{2b}+1)
            float zx = __fdividef(1.f, 1.f + __expf(ax));
            float zy = __fdividef(1.f, 1.f + __expf(ay));
            float tx = 1.f - 2.f * __fdividef(1.f, 1.f + __expf(2.f * bx));
            float ty = 1.f - 2.f * __fdividef(1.f, 1.f + __expf(2.f * by));
            float pw = g_probs[p];
            hx += pw * zx * tx;
            hy += pw * zy * ty;
        }
        hx = fmaxf(hx, 0.f);
        hy = fmaxf(hy, 0.f);
        *(float2*)&g_H[n * 64 + 2 * lane] = make_float2(hx, hy);
    }
    atomicAdd(&bsum[2 * lane],     hx);
    atomicAdd(&bsum[2 * lane + 1], hy);
    atomicAdd(&bsq[2 * lane],      hx * hx);
    atomicAdd(&bsq[2 * lane + 1],  hy * hy);
    __syncthreads();
    if (threadIdx.x < 64) {
        atomicAdd(&g_sums[threadIdx.x],  bsum[threadIdx.x]);
        atomicAdd(&g_sumsq[threadIdx.x], bsq[threadIdx.x]);
    }
}

// ---------------- fold BN into the combined output matrix -----------------
__global__ void k_pre2(const float* __restrict__ gamma, const float* __restrict__ beta) {
    __shared__ float ss[64], st[64];
    int tid = threadIdx.x;
    if (tid < 64) {
        float mean = g_sums[tid] * (1.0f / (float)NN);
        float var  = g_sumsq[tid] * (1.0f / (float)NN) - mean * mean;
        float s = gamma[tid] * rsqrtf(var + 1e-5f);
        ss[tid] = s;
        st[tid] = beta[tid] - mean * s;
    }
    __syncthreads();
    for (int idx = tid; idx < 64 * 96; idx += blockDim.x)
        g_Weff[idx] = ss[idx / 96] * g_Wc[idx];
    for (int j = tid; j < 96; j += blockDim.x) {
        float s = g_bc[j];
        for (int k = 0; k < 64; k++) s += st[k] * g_Wc[k * 96 + j];
        g_beff[j] = s;
    }
}

// ---------------- final: out = relu(H) @ W_eff + b_eff  (warp per node) ---
__global__ void k_out(float* __restrict__ out) {
    __shared__ float sW[64 * 96];
    __shared__ float sb[96];
    for (int idx = threadIdx.x; idx < 64 * 96; idx += blockDim.x) sW[idx] = g_Weff[idx];
    if (threadIdx.x < 96) sb[threadIdx.x] = g_beff[threadIdx.x];
    __syncthreads();

    int n = (blockIdx.x * blockDim.x + threadIdx.x) >> 5;
    int lane = threadIdx.x & 31;
    if (n >= NN) return;
    float2 h2 = *(const float2*)&g_H[n * 64 + 2 * lane];
    float a0 = sb[lane], a1 = sb[lane + 32], a2 = sb[lane + 64];
    #pragma unroll
    for (int i = 0; i < 64; i++) {
        float hv = __shfl_sync(0xffffffffu, (i & 1) ? h2.y : h2.x, i >> 1);
        const float* wr = &sW[i * 96];
        a0 += hv * wr[lane];
        a1 += hv * wr[lane + 32];
        a2 += hv * wr[lane + 64];
    }
    float* ob = out + n * 96;
    ob[lane] = a0; ob[lane + 32] = a1; ob[lane + 64] = a2;
}

// ---------------- launch ---------------------------------------------------
extern "C" void kernel_launch(void* const* d_in, const int* in_sizes, int n_in,
                              void* d_out, int out_size) {
    const float* x      = (const float*)d_in[0];
    const int*   ei     = (const int*)  d_in[1];
    const float* ew     = (const float*)d_in[2];
    const float* att    = (const float*)d_in[3];
    const float* conv_w = (const float*)d_in[4];
    const float* conv_b = (const float*)d_in[5];
    const float* lin_w  = (const float*)d_in[6];
    const float* lin_b  = (const float*)d_in[7];
    const float* gamma  = (const float*)d_in[8];
    const float* beta   = (const float*)d_in[9];
    const float* W1 = (const float*)d_in[10]; const float* b1 = (const float*)d_in[11];
    const float* W2 = (const float*)d_in[12]; const float* b2 = (const float*)d_in[13];
    const float* W3 = (const float*)d_in[14]; const float* b3 = (const float*)d_in[15];
    const float* W4 = (const float*)d_in[16]; const float* b4 = (const float*)d_in[17];
    const float* W5 = (const float*)d_in[18]; const float* b5 = (const float*)d_in[19];
    float* out = (float*)d_out;

    k_pre1<<<1, 256>>>(att, conv_w, conv_b, lin_w, lin_b,
                       W1, b1, W2, b2, W3, b3, W4, b4, W5, b5);
    k_deg_init<<<(NN + 255) / 256, 256>>>();
    k_deg<<<(EE + 255) / 256, 256>>>(ei, ew);
    k_dinv<<<(NN + 255) / 256, 256>>>();
    k_prepx<<<(PP * NN * 2 + 255) / 256, 256>>>(x);
    k_scatter<<<(EE * 32 + 255) / 256, 256>>>(ei, ew);
    k_H<<<NN / 8, 256>>>();
    k_pre2<<<1, 128>>>(gamma, beta);
    k_out<<<NN / 8, 256>>>(out);
}

// round 2
// speedup vs baseline: 1.4167x; 1.4167x over previous
#include <cuda_runtime.h>

#define NN 50000
#define EE 800000
#define PP 12
#define FF 8
#define HIDD 64
#define OUTD 96
#define SCAN_BLOCKS 196   // ceil(NN/256)

// ---------------- scratch (device globals; no allocation) ----------------
__device__ float  g_deg[NN];
__device__ float  g_dinv[NN];
__device__ int    g_cnt[NN];
__device__ int    g_start[NN];
__device__ int    g_cur[NN];
__device__ int    g_part[SCAN_BLOCKS];
__device__ int2   g_rec[EE];             // CSR-ordered {row, coeff}
__device__ float4 g_xT[NN * 24];         // node-major transposed x: [n][p][h] float4
__device__ float  g_H[NN * HIDD];        // relu(H_accum)
__device__ float  g_sums[HIDD];
__device__ float  g_sumsq[HIDD];
__device__ float  g_Az[FF * HIDD], g_Ah[FF * HIDD];
__device__ float  g_cz[HIDD], g_ch[HIDD];
__device__ float  g_probs[PP];
__device__ float  g_Wc[HIDD * OUTD], g_bc[OUTD];
__device__ float  g_Weff[HIDD * OUTD], g_beff[OUTD];

// ---------------- tiny precompute: fold all the small linear algebra ------
__global__ void k_pre1(const float* __restrict__ att,
                       const float* __restrict__ conv_w, const float* __restrict__ conv_b,
                       const float* __restrict__ lin_w,  const float* __restrict__ lin_b,
                       const float* __restrict__ W1, const float* __restrict__ b1,
                       const float* __restrict__ W2, const float* __restrict__ b2,
                       const float* __restrict__ W3, const float* __restrict__ b3,
                       const float* __restrict__ W4, const float* __restrict__ b4,
                       const float* __restrict__ W5, const float* __restrict__ b5) {
    int tid = threadIdx.x;
    __shared__ float sT1[64 * 32];
    __shared__ float sT2[64 * 16];
    __shared__ float sT3[64 * 8];
    __shared__ float sb[56];

    if (tid == 0) {
        float m = -1e30f;
        for (int i = 0; i < PP; i++) m = fmaxf(m, att[i]);
        float e[PP], s = 0.f;
        for (int i = 0; i < PP; i++) { e[i] = __expf(att[i] - m); s += e[i]; }
        for (int i = 0; i < PP; i++) g_probs[i] = e[i] / s;
    }

    // Az = conv_w[0] @ lin_w[0][:64],  Ah = conv_w[2] @ lin_w[2][:64]
    for (int idx = tid; idx < FF * HIDD; idx += blockDim.x) {
        int i = idx >> 6, j = idx & 63;
        float az = 0.f, ah = 0.f;
        for (int k = 0; k < HIDD; k++) {
            az += conv_w[0 * 512 + i * 64 + k] * lin_w[0 * 8192 + k * 64 + j];
            ah += conv_w[2 * 512 + i * 64 + k] * lin_w[2 * 8192 + k * 64 + j];
        }
        g_Az[idx] = az; g_Ah[idx] = ah;
    }
    for (int j = tid; j < HIDD; j += blockDim.x) {
        float cz = lin_b[0 * 64 + j], ch = lin_b[2 * 64 + j];
        for (int k = 0; k < HIDD; k++) {
            cz += conv_b[0 * 64 + k] * lin_w[0 * 8192 + k * 64 + j];
            ch += conv_b[2 * 64 + k] * lin_w[2 * 8192 + k * 64 + j];
        }
        g_cz[j] = cz; g_ch[j] = ch;
        g_sums[j] = 0.f; g_sumsq[j] = 0.f;
    }

    // Wc = W1@W2@W3@W4@W5 (64x96), bc = folded bias
    for (int idx = tid; idx < 64 * 32; idx += blockDim.x) {
        int i = idx >> 5, j = idx & 31; float s = 0.f;
        for (int k = 0; k < 64; k++) s += W1[i * 64 + k] * W2[k * 32 + j];
        sT1[idx] = s;
    }
    if (tid < 32) { float s = b2[tid]; for (int k = 0; k < 64; k++) s += b1[k] * W2[k * 32 + tid]; sb[tid] = s; }
    __syncthreads();
    for (int idx = tid; idx < 64 * 16; idx += blockDim.x) {
        int i = idx >> 4, j = idx & 15; float s = 0.f;
        for (int k = 0; k < 32; k++) s += sT1[i * 32 + k] * W3[k * 16 + j];
        sT2[idx] = s;
    }
    if (tid < 16) { float s = b3[tid]; for (int k = 0; k < 32; k++) s += sb[k] * W3[k * 16 + tid]; sb[32 + tid] = s; }
    __syncthreads();
    for (int idx = tid; idx < 64 * 8; idx += blockDim.x) {
        int i = idx >> 3, j = idx & 7; float s = 0.f;
        for (int k = 0; k < 16; k++) s += sT2[i * 16 + k] * W4[k * 8 + j];
        sT3[idx] = s;
    }
    if (tid < 8) { float s = b4[tid]; for (int k = 0; k < 16; k++) s += sb[32 + k] * W4[k * 8 + tid]; sb[48 + tid] = s; }
    __syncthreads();
    for (int idx = tid; idx < 64 * 96; idx += blockDim.x) {
        int i = idx / 96, j = idx - i * 96; float s = 0.f;
        for (int k = 0; k < 8; k++) s += sT3[i * 8 + k] * W5[k * 96 + j];
        g_Wc[idx] = s;
    }
    for (int j = tid; j < 96; j += blockDim.x) {
        float s = b5[j];
        for (int k = 0; k < 8; k++) s += sb[48 + k] * W5[k * 96 + j];
        g_bc[j] = s;
    }
}

// ---------------- init / degree+count / dinv ------------------------------
__global__ void k_init() {
    int n = blockIdx.x * blockDim.x + threadIdx.x;
    if (n < NN) { g_deg[n] = 1.0f; g_cnt[n] = 0; }
}
__global__ void k_count(const int* __restrict__ ei, const float* __restrict__ ew) {
    int e = blockIdx.x * blockDim.x + threadIdx.x;
    if (e < EE) {
        int col = ei[EE + e];
        atomicAdd(&g_deg[col], ew[e]);
        atomicAdd(&g_cnt[col], 1);
    }
}
__global__ void k_dinv() {
    int n = blockIdx.x * blockDim.x + threadIdx.x;
    if (n < NN) g_dinv[n] = rsqrtf(g_deg[n]);
}

// ---------------- 3-pass exclusive scan of g_cnt --------------------------
__global__ void k_scan1() {      // per-block sums
    int i = blockIdx.x * 256 + threadIdx.x;
    int v = (i < NN) ? g_cnt[i] : 0;
    __shared__ int ws[8];
    int s = v;
    #pragma unroll
    for (int o = 16; o; o >>= 1) s += __shfl_down_sync(0xffffffffu, s, o);
    if ((threadIdx.x & 31) == 0) ws[threadIdx.x >> 5] = s;
    __syncthreads();
    if (threadIdx.x == 0) {
        int t = 0;
        #pragma unroll
        for (int k = 0; k < 8; k++) t += ws[k];
        g_part[blockIdx.x] = t;
    }
}
__global__ void k_scan2() {      // exclusive scan of block sums (1 block)
    __shared__ int s[256];
    int t = threadIdx.x;
    int v0 = (t < SCAN_BLOCKS) ? g_part[t] : 0;
    s[t] = v0;
    __syncthreads();
    for (int off = 1; off < 256; off <<= 1) {
        int v = (t >= off) ? s[t - off] : 0;
        __syncthreads();
        s[t] += v;
        __syncthreads();
    }
    if (t < SCAN_BLOCKS) g_part[t] = s[t] - v0;
}
__global__ void k_scan3() {      // per-element exclusive scan + offsets
    __shared__ int s[256];
    int t = threadIdx.x;
    int i = blockIdx.x * 256 + t;
    int v0 = (i < NN) ? g_cnt[i] : 0;
    s[t] = v0;
    __syncthreads();
    for (int off = 1; off < 256; off <<= 1) {
        int v = (t >= off) ? s[t - off] : 0;
        __syncthreads();
        s[t] += v;
        __syncthreads();
    }
    if (i < NN) {
        int ex = s[t] - v0 + g_part[blockIdx.x];
        g_start[i] = ex;
        g_cur[i] = ex;
    }
}

// ---------------- fill CSR records {row, coeff} ---------------------------
__global__ void k_fill(const int* __restrict__ ei, const float* __restrict__ ew) {
    int e = blockIdx.x * blockDim.x + threadIdx.x;
    if (e >= EE) return;
    int row = ei[e];
    int col = ei[EE + e];
    float c = g_dinv[row] * ew[e] * g_dinv[col];
    int pos = atomicAdd(&g_cur[col], 1);
    g_rec[pos] = make_int2(row, __float_as_int(c));
}

// ---------------- transpose x to node-major [n][p][h]float4 ---------------
__global__ void k_prepx(const float* __restrict__ x) {
    __shared__ float s[32 * 96];
    int blockNode = blockIdx.x * 32;
    int lim = (NN - blockNode) * 96;     // floats valid in this block
    for (int i = threadIdx.x; i < 32 * 96; i += 256)
        s[i] = (i < lim) ? x[blockNode * 96 + i] : 0.f;
    __syncthreads();
    #pragma unroll
    for (int k = 0; k < 3; k++) {
        int o = threadIdx.x + k * 256;   // 0..767 = 32 nodes * 24 float4
        int ln = o / 24, l = o - ln * 24;
        int n = blockNode + ln;
        if (n < NN) {
            int p = l >> 1, f0 = (l & 1) * 4;
            float4 v;
            v.x = s[ln * 96 + (f0 + 0) * 12 + p];
            v.y = s[ln * 96 + (f0 + 1) * 12 + p];
            v.z = s[ln * 96 + (f0 + 2) * 12 + p];
            v.w = s[ln * 96 + (f0 + 3) * 12 + p];
            g_xT[n * 24 + l] = v;
        }
    }
}

// ---------------- FUSED: CSR gather + collapsed GRU + BN stats ------------
__global__ void __launch_bounds__(256) k_fused() {
    __shared__ float bsum[64], bsq[64];
    if (threadIdx.x < 64) { bsum[threadIdx.x] = 0.f; bsq[threadIdx.x] = 0.f; }
    __syncthreads();

    int n = (blockIdx.x * blockDim.x + threadIdx.x) >> 5;   // grid sized so n < NN
    int lane = threadIdx.x & 31;

    // --- gather: acc = self + sum_e c_e * xT[row_e], lane<24 holds float4 ---
    float4 acc = make_float4(0.f, 0.f, 0.f, 0.f);
    float dn = g_dinv[n];
    if (lane < 24) {
        float4 v = g_xT[n * 24 + lane];
        float sn = dn * dn;
        acc.x = sn * v.x; acc.y = sn * v.y; acc.z = sn * v.z; acc.w = sn * v.w;
    }
    int start = g_start[n];
    int end = start + g_cnt[n];
    int e = start;
    for (; e + 2 <= end; e += 2) {
        int2 r0 = g_rec[e];
        int2 r1 = g_rec[e + 1];
        if (lane < 24) {
            float4 v0 = g_xT[r0.x * 24 + lane];
            float4 v1 = g_xT[r1.x * 24 + lane];
            float c0 = __int_as_float(r0.y);
            float c1 = __int_as_float(r1.y);
            acc.x = fmaf(c0, v0.x, acc.x); acc.y = fmaf(c0, v0.y, acc.y);
            acc.z = fmaf(c0, v0.z, acc.z); acc.w = fmaf(c0, v0.w, acc.w);
            acc.x = fmaf(c1, v1.x, acc.x); acc.y = fmaf(c1, v1.y, acc.y);
            acc.z = fmaf(c1, v1.z, acc.z); acc.w = fmaf(c1, v1.w, acc.w);
        }
    }
    if (e < end) {
        int2 r0 = g_rec[e];
        if (lane < 24) {
            float4 v0 = g_xT[r0.x * 24 + lane];
            float c0 = __int_as_float(r0.y);
            acc.x = fmaf(c0, v0.x, acc.x); acc.y = fmaf(c0, v0.y, acc.y);
            acc.z = fmaf(c0, v0.z, acc.z); acc.w = fmaf(c0, v0.w, acc.w);
        }
    }

    // --- collapsed GRU over periods; lane computes hidden dims 2*lane,2*lane+1 ---
    float2 az[8], ah[8];
    #pragma unroll
    for (int i = 0; i < 8; i++) {
        az[i] = *(const float2*)&g_Az[i * 64 + 2 * lane];
        ah[i] = *(const float2*)&g_Ah[i * 64 + 2 * lane];
    }
    float2 cz = *(const float2*)&g_cz[2 * lane];
    float2 ch = *(const float2*)&g_ch[2 * lane];

    float hx = 0.f, hy = 0.f;
    #pragma unroll
    for (int p = 0; p < PP; p++) {
        int s0 = 2 * p, s1 = 2 * p + 1;
        float u[8];
        u[0] = __shfl_sync(0xffffffffu, acc.x, s0);
        u[1] = __shfl_sync(0xffffffffu, acc.y, s0);
        u[2] = __shfl_sync(0xffffffffu, acc.z, s0);
        u[3] = __shfl_sync(0xffffffffu, acc.w, s0);
        u[4] = __shfl_sync(0xffffffffu, acc.x, s1);
        u[5] = __shfl_sync(0xffffffffu, acc.y, s1);
        u[6] = __shfl_sync(0xffffffffu, acc.z, s1);
        u[7] = __shfl_sync(0xffffffffu, acc.w, s1);
        float ax = cz.x, ay = cz.y, bx = ch.x, by = ch.y;
        #pragma unroll
        for (int i = 0; i < 8; i++) {
            ax = fmaf(u[i], az[i].x, ax);  ay = fmaf(u[i], az[i].y, ay);
            bx = fmaf(u[i], ah[i].x, bx);  by = fmaf(u[i], ah[i].y, by);
        }
        float zx = __fdividef(1.f, 1.f + __expf(ax));
        float zy = __fdividef(1.f, 1.f + __expf(ay));
        float tx = 1.f - 2.f * __fdividef(1.f, 1.f + __expf(2.f * bx));
        float ty = 1.f - 2.f * __fdividef(1.f, 1.f + __expf(2.f * by));
        float pw = g_probs[p];
        hx = fmaf(pw, zx * tx, hx);
        hy = fmaf(pw, zy * ty, hy);
    }
    hx = fmaxf(hx, 0.f);
    hy = fmaxf(hy, 0.f);
    *(float2*)&g_H[n * 64 + 2 * lane] = make_float2(hx, hy);

    atomicAdd(&bsum[2 * lane],     hx);
    atomicAdd(&bsum[2 * lane + 1], hy);
    atomicAdd(&bsq[2 * lane],      hx * hx);
    atomicAdd(&bsq[2 * lane + 1],  hy * hy);
    __syncthreads();
    if (threadIdx.x < 64) {
        atomicAdd(&g_sums[threadIdx.x],  bsum[threadIdx.x]);
        atomicAdd(&g_sumsq[threadIdx.x], bsq[threadIdx.x]);
    }
}

// ---------------- fold BN into the combined output matrix -----------------
__global__ void k_pre2(const float* __restrict__ gamma, const float* __restrict__ beta) {
    __shared__ float ss[64], st[64];
    int tid = threadIdx.x;
    if (tid < 64) {
        float mean = g_sums[tid] * (1.0f / (float)NN);
        float var  = g_sumsq[tid] * (1.0f / (float)NN) - mean * mean;
        float s = gamma[tid] * rsqrtf(var + 1e-5f);
        ss[tid] = s;
        st[tid] = beta[tid] - mean * s;
    }
    __syncthreads();
    for (int idx = tid; idx < 64 * 96; idx += blockDim.x)
        g_Weff[idx] = ss[idx / 96] * g_Wc[idx];
    for (int j = tid; j < 96; j += blockDim.x) {
        float s = g_bc[j];
        for (int k = 0; k < 64; k++) s += st[k] * g_Wc[k * 96 + j];
        g_beff[j] = s;
    }
}

// ---------------- final: out = relu(H) @ W_eff + b_eff --------------------
__global__ void __launch_bounds__(256) k_out(float* __restrict__ out) {
    __shared__ float sW[64 * 96];
    __shared__ float sb[96];
    for (int idx = threadIdx.x; idx < 64 * 96; idx += blockDim.x) sW[idx] = g_Weff[idx];
    if (threadIdx.x < 96) sb[threadIdx.x] = g_beff[threadIdx.x];
    __syncthreads();

    int n = (blockIdx.x * blockDim.x + threadIdx.x) >> 5;
    int lane = threadIdx.x & 31;
    if (n >= NN) return;
    float2 h2 = *(const float2*)&g_H[n * 64 + 2 * lane];
    float a0 = sb[lane], a1 = sb[lane + 32], a2 = sb[lane + 64];
    #pragma unroll
    for (int i = 0; i < 64; i++) {
        float hv = __shfl_sync(0xffffffffu, (i & 1) ? h2.y : h2.x, i >> 1);
        const float* wr = &sW[i * 96];
        a0 = fmaf(hv, wr[lane],      a0);
        a1 = fmaf(hv, wr[lane + 32], a1);
        a2 = fmaf(hv, wr[lane + 64], a2);
    }
    float* ob = out + n * 96;
    ob[lane] = a0; ob[lane + 32] = a1; ob[lane + 64] = a2;
}

// ---------------- launch ---------------------------------------------------
extern "C" void kernel_launch(void* const* d_in, const int* in_sizes, int n_in,
                              void* d_out, int out_size) {
    const float* x      = (const float*)d_in[0];
    const int*   ei     = (const int*)  d_in[1];
    const float* ew     = (const float*)d_in[2];
    const float* att    = (const float*)d_in[3];
    const float* conv_w = (const float*)d_in[4];
    const float* conv_b = (const float*)d_in[5];
    const float* lin_w  = (const float*)d_in[6];
    const float* lin_b  = (const float*)d_in[7];
    const float* gamma  = (const float*)d_in[8];
    const float* beta   = (const float*)d_in[9];
    const float* W1 = (const float*)d_in[10]; const float* b1 = (const float*)d_in[11];
    const float* W2 = (const float*)d_in[12]; const float* b2 = (const float*)d_in[13];
    const float* W3 = (const float*)d_in[14]; const float* b3 = (const float*)d_in[15];
    const float* W4 = (const float*)d_in[16]; const float* b4 = (const float*)d_in[17];
    const float* W5 = (const float*)d_in[18]; const float* b5 = (const float*)d_in[19];
    float* out = (float*)d_out;

    k_pre1<<<1, 256>>>(att, conv_w, conv_b, lin_w, lin_b,
                       W1, b1, W2, b2, W3, b3, W4, b4, W5, b5);
    k_init<<<(NN + 255) / 256, 256>>>();
    k_prepx<<<(NN + 31) / 32, 256>>>(x);
    k_count<<<(EE + 255) / 256, 256>>>(ei, ew);
    k_dinv<<<(NN + 255) / 256, 256>>>();
    k_scan1<<<SCAN_BLOCKS, 256>>>();
    k_scan2<<<1, 256>>>();
    k_scan3<<<SCAN_BLOCKS, 256>>>();
    k_fill<<<(EE + 255) / 256, 256>>>(ei, ew);
    k_fused<<<NN / 8, 256>>>();
    k_pre2<<<1, 128>>>(gamma, beta);
    k_out<<<NN / 8, 256>>>(out);
}

// round 3
// speedup vs baseline: 1.5955x; 1.1262x over previous
#include <cuda_runtime.h>
#include <cuda_fp16.h>

#define NN 50000
#define EE 800000
#define PP 12
#define FF 8
#define HIDD 64
#define OUTD 96
#define SCAN_BLOCKS 196   // ceil(NN/256)

// ---------------- scratch (device globals; no allocation) ----------------
__device__ float2 g_degcnt[NN];          // .x = deg(+1 self), .y = edge count (as float)
__device__ float  g_dinv[NN];
__device__ int    g_cnt[NN];
__device__ int    g_start[NN];
__device__ int    g_cur[NN];
__device__ int    g_part[SCAN_BLOCKS];
__device__ int2   g_rec[EE];             // CSR-ordered {row, coeff-bits}
__device__ uint4  g_xTh[NN * 12];        // node-major fp16 features: chunk c = period c, f0..7
__device__ float  g_H[NN * HIDD];        // relu(H_accum)
__device__ float  g_sums[HIDD];
__device__ float  g_sumsq[HIDD];
__device__ float  g_Az[FF * HIDD], g_Ah[FF * HIDD];
__device__ float  g_cz[HIDD], g_ch[HIDD];
__device__ float  g_probs[PP];
__device__ float  g_Wc[HIDD * OUTD], g_bc[OUTD];
__device__ float  g_Weff[HIDD * OUTD], g_beff[OUTD];

// ---------------- tiny precompute: fold all the small linear algebra ------
__global__ void k_pre1(const float* __restrict__ att,
                       const float* __restrict__ conv_w, const float* __restrict__ conv_b,
                       const float* __restrict__ lin_w,  const float* __restrict__ lin_b,
                       const float* __restrict__ W1, const float* __restrict__ b1,
                       const float* __restrict__ W2, const float* __restrict__ b2,
                       const float* __restrict__ W3, const float* __restrict__ b3,
                       const float* __restrict__ W4, const float* __restrict__ b4,
                       const float* __restrict__ W5, const float* __restrict__ b5) {
    int tid = threadIdx.x;
    __shared__ float sT1[64 * 32];
    __shared__ float sT2[64 * 16];
    __shared__ float sT3[64 * 8];
    __shared__ float sb[56];

    if (tid == 0) {
        float m = -1e30f;
        for (int i = 0; i < PP; i++) m = fmaxf(m, att[i]);
        float e[PP], s = 0.f;
        for (int i = 0; i < PP; i++) { e[i] = __expf(att[i] - m); s += e[i]; }
        for (int i = 0; i < PP; i++) g_probs[i] = e[i] / s;
    }

    // Az = conv_w[0] @ lin_w[0][:64],  Ah = conv_w[2] @ lin_w[2][:64]
    for (int idx = tid; idx < FF * HIDD; idx += blockDim.x) {
        int i = idx >> 6, j = idx & 63;
        float az = 0.f, ah = 0.f;
        for (int k = 0; k < HIDD; k++) {
            az += conv_w[0 * 512 + i * 64 + k] * lin_w[0 * 8192 + k * 64 + j];
            ah += conv_w[2 * 512 + i * 64 + k] * lin_w[2 * 8192 + k * 64 + j];
        }
        g_Az[idx] = az; g_Ah[idx] = ah;
    }
    for (int j = tid; j < HIDD; j += blockDim.x) {
        float cz = lin_b[0 * 64 + j], ch = lin_b[2 * 64 + j];
        for (int k = 0; k < HIDD; k++) {
            cz += conv_b[0 * 64 + k] * lin_w[0 * 8192 + k * 64 + j];
            ch += conv_b[2 * 64 + k] * lin_w[2 * 8192 + k * 64 + j];
        }
        g_cz[j] = cz; g_ch[j] = ch;
        g_sums[j] = 0.f; g_sumsq[j] = 0.f;
    }

    // Wc = W1@W2@W3@W4@W5 (64x96), bc = folded bias
    for (int idx = tid; idx < 64 * 32; idx += blockDim.x) {
        int i = idx >> 5, j = idx & 31; float s = 0.f;
        for (int k = 0; k < 64; k++) s += W1[i * 64 + k] * W2[k * 32 + j];
        sT1[idx] = s;
    }
    if (tid < 32) { float s = b2[tid]; for (int k = 0; k < 64; k++) s += b1[k] * W2[k * 32 + tid]; sb[tid] = s; }
    __syncthreads();
    for (int idx = tid; idx < 64 * 16; idx += blockDim.x) {
        int i = idx >> 4, j = idx & 15; float s = 0.f;
        for (int k = 0; k < 32; k++) s += sT1[i * 32 + k] * W3[k * 16 + j];
        sT2[idx] = s;
    }
    if (tid < 16) { float s = b3[tid]; for (int k = 0; k < 32; k++) s += sb[k] * W3[k * 16 + tid]; sb[32 + tid] = s; }
    __syncthreads();
    for (int idx = tid; idx < 64 * 8; idx += blockDim.x) {
        int i = idx >> 3, j = idx & 7; float s = 0.f;
        for (int k = 0; k < 16; k++) s += sT2[i * 16 + k] * W4[k * 8 + j];
        sT3[idx] = s;
    }
    if (tid < 8) { float s = b4[tid]; for (int k = 0; k < 16; k++) s += sb[32 + k] * W4[k * 8 + tid]; sb[48 + tid] = s; }
    __syncthreads();
    for (int idx = tid; idx < 64 * 96; idx += blockDim.x) {
        int i = idx / 96, j = idx - i * 96; float s = 0.f;
        for (int k = 0; k < 8; k++) s += sT3[i * 8 + k] * W5[k * 96 + j];
        g_Wc[idx] = s;
    }
    for (int j = tid; j < 96; j += blockDim.x) {
        float s = b5[j];
        for (int k = 0; k < 8; k++) s += sb[48 + k] * W5[k * 96 + j];
        g_bc[j] = s;
    }
}

// ---------------- transpose x to node-major fp16 + init deg/cnt -----------
__global__ void k_prepx(const float* __restrict__ x) {
    __shared__ float s[32 * 96];
    int blockNode = blockIdx.x * 32;

    int gi = blockIdx.x * blockDim.x + threadIdx.x;     // grid covers >= NN threads
    if (gi < NN) g_degcnt[gi] = make_float2(1.0f, 0.0f);

    int lim = (NN - blockNode) * 96;
    for (int i = threadIdx.x; i < 32 * 96; i += 256)
        s[i] = (i < lim) ? x[blockNode * 96 + i] : 0.f;
    __syncthreads();
    #pragma unroll
    for (int k = 0; k < 2; k++) {
        int o = threadIdx.x + k * 256;                  // 0..383 = 32 nodes * 12 chunks
        if (o < 32 * 12) {
            int ln = o / 12, p = o - ln * 12;
            int n = blockNode + ln;
            if (n < NN) {
                __align__(16) __half hv[8];
                #pragma unroll
                for (int f = 0; f < 8; f++)
                    hv[f] = __float2half_rn(s[ln * 96 + f * 12 + p]);
                g_xTh[n * 12 + p] = *(const uint4*)hv;
            }
        }
    }
}

// ---------------- degree + count with one vector reduction ----------------
__global__ void k_count(const int* __restrict__ ei, const float* __restrict__ ew) {
    int e = blockIdx.x * blockDim.x + threadIdx.x;
    if (e < EE) {
        int col = ei[EE + e];
        float w = ew[e];
        float2* dst = &g_degcnt[col];
        asm volatile("red.global.add.v2.f32 [%0], {%1, %2};"
                     :: "l"(dst), "f"(w), "f"(1.0f) : "memory");
    }
}

// ---------------- scan pass 1 (+ dinv) ------------------------------------
__global__ void k_scan1() {
    int i = blockIdx.x * 256 + threadIdx.x;
    int v = 0;
    if (i < NN) {
        float2 dc = g_degcnt[i];
        g_dinv[i] = rsqrtf(dc.x);
        v = (int)dc.y;
        g_cnt[i] = v;
    }
    __shared__ int ws[8];
    int s = v;
    #pragma unroll
    for (int o = 16; o; o >>= 1) s += __shfl_down_sync(0xffffffffu, s, o);
    if ((threadIdx.x & 31) == 0) ws[threadIdx.x >> 5] = s;
    __syncthreads();
    if (threadIdx.x == 0) {
        int t = 0;
        #pragma unroll
        for (int k = 0; k < 8; k++) t += ws[k];
        g_part[blockIdx.x] = t;
    }
}
__global__ void k_scan2() {
    __shared__ int s[256];
    int t = threadIdx.x;
    int v0 = (t < SCAN_BLOCKS) ? g_part[t] : 0;
    s[t] = v0;
    __syncthreads();
    for (int off = 1; off < 256; off <<= 1) {
        int v = (t >= off) ? s[t - off] : 0;
        __syncthreads();
        s[t] += v;
        __syncthreads();
    }
    if (t < SCAN_BLOCKS) g_part[t] = s[t] - v0;
}
__global__ void k_scan3() {
    __shared__ int s[256];
    int t = threadIdx.x;
    int i = blockIdx.x * 256 + t;
    int v0 = (i < NN) ? g_cnt[i] : 0;
    s[t] = v0;
    __syncthreads();
    for (int off = 1; off < 256; off <<= 1) {
        int v = (t >= off) ? s[t - off] : 0;
        __syncthreads();
        s[t] += v;
        __syncthreads();
    }
    if (i < NN) {
        int ex = s[t] - v0 + g_part[blockIdx.x];
        g_start[i] = ex;
        g_cur[i] = ex;
    }
}

// ---------------- fill CSR records {row, coeff} ---------------------------
__global__ void k_fill(const int* __restrict__ ei, const float* __restrict__ ew) {
    int e = blockIdx.x * blockDim.x + threadIdx.x;
    if (e >= EE) return;
    int row = ei[e];
    int col = ei[EE + e];
    float c = g_dinv[row] * ew[e] * g_dinv[col];
    int pos = atomicAdd(&g_cur[col], 1);
    g_rec[pos] = make_int2(row, __float_as_int(c));
}

// ---------------- fp16 chunk FMA into fp32 acc ----------------------------
__device__ __forceinline__ void h8_fma(float acc[8], uint4 v, float c) {
    const __half2* h = (const __half2*)&v;
    #pragma unroll
    for (int i = 0; i < 4; i++) {
        float2 f = __half22float2(h[i]);
        acc[2 * i]     = fmaf(c, f.x, acc[2 * i]);
        acc[2 * i + 1] = fmaf(c, f.y, acc[2 * i + 1]);
    }
}

// ---------------- FUSED: CSR gather + collapsed GRU + BN stats ------------
__global__ void __launch_bounds__(256) k_fused() {
    __shared__ float bsum[64], bsq[64];
    if (threadIdx.x < 64) { bsum[threadIdx.x] = 0.f; bsq[threadIdx.x] = 0.f; }
    __syncthreads();

    int n = (blockIdx.x * blockDim.x + threadIdx.x) >> 5;   // grid sized so n < NN
    int lane = threadIdx.x & 31;
    bool act = lane < 24;
    int grp = (lane >= 12) ? 1 : 0;          // which edge of a pair
    int sub = lane - grp * 12;               // period chunk 0..11

    float acc[8] = {0.f, 0.f, 0.f, 0.f, 0.f, 0.f, 0.f, 0.f};
    float dn = g_dinv[n];
    if (lane < 12) {                          // self-loop term
        uint4 v = g_xTh[n * 12 + sub];
        h8_fma(acc, v, dn * dn);
    }

    int start = g_start[n];
    int end = start + g_cnt[n];
    int e = start;
    // 4 edges per iteration: grp picks within each pair
    for (; e + 4 <= end; e += 4) {
        if (act) {
            int2 r0 = g_rec[e + grp];
            int2 r1 = g_rec[e + 2 + grp];
            uint4 v0 = g_xTh[r0.x * 12 + sub];
            uint4 v1 = g_xTh[r1.x * 12 + sub];
            h8_fma(acc, v0, __int_as_float(r0.y));
            h8_fma(acc, v1, __int_as_float(r1.y));
        }
    }
    for (; e < end; e += 2) {
        if (act && e + grp < end) {
            int2 r0 = g_rec[e + grp];
            uint4 v0 = g_xTh[r0.x * 12 + sub];
            h8_fma(acc, v0, __int_as_float(r0.y));
        }
    }
    // combine even/odd edge partials: lanes 0..11 += lanes 12..23
    #pragma unroll
    for (int i = 0; i < 8; i++)
        acc[i] += __shfl_down_sync(0xffffffffu, acc[i], 12);

    // --- collapsed GRU; lane computes hidden dims 2*lane, 2*lane+1 ---
    float2 az[8], ah[8];
    #pragma unroll
    for (int i = 0; i < 8; i++) {
        az[i] = *(const float2*)&g_Az[i * 64 + 2 * lane];
        ah[i] = *(const float2*)&g_Ah[i * 64 + 2 * lane];
    }
    float2 cz = *(const float2*)&g_cz[2 * lane];
    float2 ch = *(const float2*)&g_ch[2 * lane];

    float hx = 0.f, hy = 0.f;
    #pragma unroll
    for (int p = 0; p < PP; p++) {
        float u[8];
        #pragma unroll
        for (int i = 0; i < 8; i++)
            u[i] = __shfl_sync(0xffffffffu, acc[i], p);
        float ax = cz.x, ay = cz.y, bx = ch.x, by = ch.y;
        #pragma unroll
        for (int i = 0; i < 8; i++) {
            ax = fmaf(u[i], az[i].x, ax);  ay = fmaf(u[i], az[i].y, ay);
            bx = fmaf(u[i], ah[i].x, bx);  by = fmaf(u[i], ah[i].y, by);
        }
        float zx = __fdividef(1.f, 1.f + __expf(ax));
        float zy = __fdividef(1.f, 1.f + __expf(ay));
        float tx = 1.f - 2.f * __fdividef(1.f, 1.f + __expf(2.f * bx));
        float ty = 1.f - 2.f * __fdividef(1.f, 1.f + __expf(2.f * by));
        float pw = g_probs[p];
        hx = fmaf(pw, zx * tx, hx);
        hy = fmaf(pw, zy * ty, hy);
    }
    hx = fmaxf(hx, 0.f);
    hy = fmaxf(hy, 0.f);
    *(float2*)&g_H[n * 64 + 2 * lane] = make_float2(hx, hy);

    atomicAdd(&bsum[2 * lane],     hx);
    atomicAdd(&bsum[2 * lane + 1], hy);
    atomicAdd(&bsq[2 * lane],      hx * hx);
    atomicAdd(&bsq[2 * lane + 1],  hy * hy);
    __syncthreads();
    if (threadIdx.x < 64) {
        atomicAdd(&g_sums[threadIdx.x],  bsum[threadIdx.x]);
        atomicAdd(&g_sumsq[threadIdx.x], bsq[threadIdx.x]);
    }
}

// ---------------- fold BN into the combined output matrix -----------------
__global__ void k_pre2(const float* __restrict__ gamma, const float* __restrict__ beta) {
    __shared__ float ss[64], st[64];
    int tid = threadIdx.x;
    if (tid < 64) {
        float mean = g_sums[tid] * (1.0f / (float)NN);
        float var  = g_sumsq[tid] * (1.0f / (float)NN) - mean * mean;
        float s = gamma[tid] * rsqrtf(var + 1e-5f);
        ss[tid] = s;
        st[tid] = beta[tid] - mean * s;
    }
    __syncthreads();
    for (int idx = tid; idx < 64 * 96; idx += blockDim.x)
        g_Weff[idx] = ss[idx / 96] * g_Wc[idx];
    for (int j = tid; j < 96; j += blockDim.x) {
        float s = g_bc[j];
        for (int k = 0; k < 64; k++) s += st[k] * g_Wc[k * 96 + j];
        g_beff[j] = s;
    }
}

// ---------------- final: out = relu(H) @ W_eff + b_eff --------------------
__global__ void __launch_bounds__(256) k_out(float* __restrict__ out) {
    __shared__ float sW[64 * 96];
    __shared__ float sb[96];
    for (int idx = threadIdx.x; idx < 64 * 96; idx += blockDim.x) sW[idx] = g_Weff[idx];
    if (threadIdx.x < 96) sb[threadIdx.x] = g_beff[threadIdx.x];
    __syncthreads();

    int n = (blockIdx.x * blockDim.x + threadIdx.x) >> 5;
    int lane = threadIdx.x & 31;
    if (n >= NN) return;
    float2 h2 = *(const float2*)&g_H[n * 64 + 2 * lane];
    float a0 = sb[lane], a1 = sb[lane + 32], a2 = sb[lane + 64];
    #pragma unroll
    for (int i = 0; i < 64; i++) {
        float hv = __shfl_sync(0xffffffffu, (i & 1) ? h2.y : h2.x, i >> 1);
        const float* wr = &sW[i * 96];
        a0 = fmaf(hv, wr[lane],      a0);
        a1 = fmaf(hv, wr[lane + 32], a1);
        a2 = fmaf(hv, wr[lane + 64], a2);
    }
    float* ob = out + n * 96;
    ob[lane] = a0; ob[lane + 32] = a1; ob[lane + 64] = a2;
}

// ---------------- launch ---------------------------------------------------
extern "C" void kernel_launch(void* const* d_in, const int* in_sizes, int n_in,
                              void* d_out, int out_size) {
    const float* x      = (const float*)d_in[0];
    const int*   ei     = (const int*)  d_in[1];
    const float* ew     = (const float*)d_in[2];
    const float* att    = (const float*)d_in[3];
    const float* conv_w = (const float*)d_in[4];
    const float* conv_b = (const float*)d_in[5];
    const float* lin_w  = (const float*)d_in[6];
    const float* lin_b  = (const float*)d_in[7];
    const float* gamma  = (const float*)d_in[8];
    const float* beta   = (const float*)d_in[9];
    const float* W1 = (const float*)d_in[10]; const float* b1 = (const float*)d_in[11];
    const float* W2 = (const float*)d_in[12]; const float* b2 = (const float*)d_in[13];
    const float* W3 = (const float*)d_in[14]; const float* b3 = (const float*)d_in[15];
    const float* W4 = (const float*)d_in[16]; const float* b4 = (const float*)d_in[17];
    const float* W5 = (const float*)d_in[18]; const float* b5 = (const float*)d_in[19];
    float* out = (float*)d_out;

    k_pre1<<<1, 256>>>(att, conv_w, conv_b, lin_w, lin_b,
                       W1, b1, W2, b2, W3, b3, W4, b4, W5, b5);
    k_prepx<<<(NN + 31) / 32, 256>>>(x);
    k_count<<<(EE + 255) / 256, 256>>>(ei, ew);
    k_scan1<<<SCAN_BLOCKS, 256>>>();
    k_scan2<<<1, 256>>>();
    k_scan3<<<SCAN_BLOCKS, 256>>>();
    k_fill<<<(EE + 255) / 256, 256>>>(ei, ew);
    k_fused<<<NN / 8, 256>>>();
    k_pre2<<<1, 128>>>(gamma, beta);
    k_out<<<NN / 8, 256>>>(out);
}

// round 4
// speedup vs baseline: 1.7611x; 1.1038x over previous
#include <cuda_runtime.h>
#include <cuda_fp16.h>

#define NN 50000
#define EE 800000
#define PP 12
#define SCAN_BLOCKS 196      // ceil(NN/256)
#define PREPX_BLOCKS 1563    // ceil(NN/32)
#define FUSED_BLOCKS 888     // 148 * 6
#define OUT_BLOCKS 888

// ---------------- scratch (device globals; no allocation) ----------------
__device__ float2 g_degcnt[NN];          // .x = deg(+1 self), .y = in-edge count
__device__ int    g_start[NN];
__device__ int    g_cur[NN];
__device__ int    g_part[SCAN_BLOCKS];
__device__ int2   g_rec[EE];             // CSR-ordered {row, ew-bits}
__device__ uint4  g_xTh[NN * 12];        // node-major fp16: after scanB, scaled by dinv[n]
__device__ float  g_H[NN * 64];          // relu(H_accum)
__device__ float  g_sums[64];
__device__ float  g_sumsq[64];
__device__ float  g_Az[8 * 64], g_Ah[8 * 64];   // Az, cz pre-folded by 0.5
__device__ float  g_cz[64], g_ch[64];
__device__ float  g_probs[PP];
__device__ float  g_Wc[64 * 96], g_bc[96];

__device__ __forceinline__ float tanha(float x) {
    float r; asm("tanh.approx.f32 %0, %1;" : "=f"(r) : "f"(x)); return r;
}

// ---------------- kernel 1: prepx (+init) on blocks 0..1562, pre1 on 1563 --
__global__ void __launch_bounds__(256) k_pre0(
        const float* __restrict__ x,
        const float* __restrict__ att,
        const float* __restrict__ conv_w, const float* __restrict__ conv_b,
        const float* __restrict__ lin_w,  const float* __restrict__ lin_b,
        const float* __restrict__ W1, const float* __restrict__ b1,
        const float* __restrict__ W2, const float* __restrict__ b2,
        const float* __restrict__ W3, const float* __restrict__ b3,
        const float* __restrict__ W4, const float* __restrict__ b4,
        const float* __restrict__ W5, const float* __restrict__ b5) {
    __shared__ __align__(16) char sm[14592];
    int tid = threadIdx.x;

    if (blockIdx.x < PREPX_BLOCKS) {
        // ---- prepx: x -> node-major fp16 (unscaled) + init degcnt ----
        float* s = (float*)sm;                      // 32*96 floats
        int blockNode = blockIdx.x * 32;
        int gi = blockIdx.x * 256 + tid;
        if (gi < NN) g_degcnt[gi] = make_float2(1.0f, 0.0f);
        int lim = (NN - blockNode) * 96;
        for (int i = tid; i < 32 * 96; i += 256)
            s[i] = (i < lim) ? x[blockNode * 96 + i] : 0.f;
        __syncthreads();
        #pragma unroll
        for (int k = 0; k < 2; k++) {
            int o = tid + k * 256;                  // 0..383 = 32 nodes * 12 chunks
            if (o < 32 * 12) {
                int ln = o / 12, p = o - ln * 12;
                int n = blockNode + ln;
                if (n < NN) {
                    __align__(16) __half hv[8];
                    #pragma unroll
                    for (int f = 0; f < 8; f++)
                        hv[f] = __float2half_rn(s[ln * 96 + f * 12 + p]);
                    g_xTh[n * 12 + p] = *(const uint4*)hv;
                }
            }
        }
        return;
    }

    // ---- pre1: fold all the small linear algebra ----
    float* sT1 = (float*)sm;           // 2048
    float* sT2 = sT1 + 2048;           // 1024
    float* sT3 = sT2 + 1024;           // 512
    float* sb  = sT3 + 512;            // 56

    if (tid == 0) {
        float m = -1e30f;
        for (int i = 0; i < PP; i++) m = fmaxf(m, att[i]);
        float e[PP], s = 0.f;
        for (int i = 0; i < PP; i++) { e[i] = __expf(att[i] - m); s += e[i]; }
        for (int i = 0; i < PP; i++) g_probs[i] = e[i] / s;
    }
    // Az = 0.5 * conv_w[0]@lin_w[0][:64],  Ah = conv_w[2]@lin_w[2][:64]
    for (int idx = tid; idx < 8 * 64; idx += 256) {
        int i = idx >> 6, j = idx & 63;
        float az = 0.f, ah = 0.f;
        for (int k = 0; k < 64; k++) {
            az += conv_w[0 * 512 + i * 64 + k] * lin_w[0 * 8192 + k * 64 + j];
            ah += conv_w[2 * 512 + i * 64 + k] * lin_w[2 * 8192 + k * 64 + j];
        }
        g_Az[idx] = 0.5f * az; g_Ah[idx] = ah;
    }
    for (int j = tid; j < 64; j += 256) {
        float cz = lin_b[0 * 64 + j], ch = lin_b[2 * 64 + j];
        for (int k = 0; k < 64; k++) {
            cz += conv_b[0 * 64 + k] * lin_w[0 * 8192 + k * 64 + j];
            ch += conv_b[2 * 64 + k] * lin_w[2 * 8192 + k * 64 + j];
        }
        g_cz[j] = 0.5f * cz; g_ch[j] = ch;
        g_sums[j] = 0.f; g_sumsq[j] = 0.f;
    }
    // Wc = W1@W2@W3@W4@W5 (64x96), bc = folded bias
    for (int idx = tid; idx < 64 * 32; idx += 256) {
        int i = idx >> 5, j = idx & 31; float s = 0.f;
        for (int k = 0; k < 64; k++) s += W1[i * 64 + k] * W2[k * 32 + j];
        sT1[idx] = s;
    }
    if (tid < 32) { float s = b2[tid]; for (int k = 0; k < 64; k++) s += b1[k] * W2[k * 32 + tid]; sb[tid] = s; }
    __syncthreads();
    for (int idx = tid; idx < 64 * 16; idx += 256) {
        int i = idx >> 4, j = idx & 15; float s = 0.f;
        for (int k = 0; k < 32; k++) s += sT1[i * 32 + k] * W3[k * 16 + j];
        sT2[idx] = s;
    }
    if (tid < 16) { float s = b3[tid]; for (int k = 0; k < 32; k++) s += sb[k] * W3[k * 16 + tid]; sb[32 + tid] = s; }
    __syncthreads();
    for (int idx = tid; idx < 64 * 8; idx += 256) {
        int i = idx >> 3, j = idx & 7; float s = 0.f;
        for (int k = 0; k < 16; k++) s += sT2[i * 16 + k] * W4[k * 8 + j];
        sT3[idx] = s;
    }
    if (tid < 8) { float s = b4[tid]; for (int k = 0; k < 16; k++) s += sb[32 + k] * W4[k * 8 + tid]; sb[48 + tid] = s; }
    __syncthreads();
    for (int idx = tid; idx < 64 * 96; idx += 256) {
        int i = idx / 96, j = idx - i * 96; float s = 0.f;
        for (int k = 0; k < 8; k++) s += sT3[i * 8 + k] * W5[k * 96 + j];
        g_Wc[idx] = s;
    }
    for (int j = tid; j < 96; j += 256) {
        float s = b5[j];
        for (int k = 0; k < 8; k++) s += sb[48 + k] * W5[k * 96 + j];
        g_bc[j] = s;
    }
}

// ---------------- kernel 2: degree + count, 4 edges/thread ----------------
__global__ void k_count(const int* __restrict__ ei, const float* __restrict__ ew) {
    int e = (blockIdx.x * blockDim.x + threadIdx.x) * 4;
    if (e < EE) {
        int4 cols = *(const int4*)&ei[EE + e];
        float4 w = *(const float4*)&ew[e];
        asm volatile("red.global.add.v2.f32 [%0], {%1, %2};"
                     :: "l"(&g_degcnt[cols.x]), "f"(w.x), "f"(1.0f) : "memory");
        asm volatile("red.global.add.v2.f32 [%0], {%1, %2};"
                     :: "l"(&g_degcnt[cols.y]), "f"(w.y), "f"(1.0f) : "memory");
        asm volatile("red.global.add.v2.f32 [%0], {%1, %2};"
                     :: "l"(&g_degcnt[cols.z]), "f"(w.z), "f"(1.0f) : "memory");
        asm volatile("red.global.add.v2.f32 [%0], {%1, %2};"
                     :: "l"(&g_degcnt[cols.w]), "f"(w.w), "f"(1.0f) : "memory");
    }
}

// ---------------- kernel 3: per-block count sums --------------------------
__global__ void k_scanA() {
    int i = blockIdx.x * 256 + threadIdx.x;
    int v = (i < NN) ? (int)g_degcnt[i].y : 0;
    __shared__ int ws[8];
    int s = v;
    #pragma unroll
    for (int o = 16; o; o >>= 1) s += __shfl_down_sync(0xffffffffu, s, o);
    if ((threadIdx.x & 31) == 0) ws[threadIdx.x >> 5] = s;
    __syncthreads();
    if (threadIdx.x == 0) {
        int t = 0;
        #pragma unroll
        for (int k = 0; k < 8; k++) t += ws[k];
        g_part[blockIdx.x] = t;
    }
}

// ---------------- kernel 4: block prefix + local scan + dinv-scale xTh ----
__global__ void __launch_bounds__(256) k_scanB() {
    __shared__ int s[256];
    __shared__ int ws[8];
    __shared__ int sprefix;
    __shared__ float sdinv[256];
    int t = threadIdx.x, b = blockIdx.x;

    // prefix over earlier blocks
    int v = (t < b) ? g_part[t] : 0;     // t < SCAN_BLOCKS implied (b <= 195)
    #pragma unroll
    for (int o = 16; o; o >>= 1) v += __shfl_down_sync(0xffffffffu, v, o);
    if ((t & 31) == 0) ws[t >> 5] = v;
    __syncthreads();
    if (t == 0) {
        int q = 0;
        #pragma unroll
        for (int k = 0; k < 8; k++) q += ws[k];
        sprefix = q;
    }

    int i = b * 256 + t;
    float2 dc = (i < NN) ? g_degcnt[i] : make_float2(1.f, 0.f);
    int c = (int)dc.y;
    sdinv[t] = rsqrtf(dc.x);
    s[t] = c;
    __syncthreads();
    for (int off = 1; off < 256; off <<= 1) {
        int u = (t >= off) ? s[t - off] : 0;
        __syncthreads();
        s[t] += u;
        __syncthreads();
    }
    if (i < NN) {
        int ex = s[t] - c + sprefix;
        g_start[i] = ex;
        g_cur[i] = ex;
    }

    // scale this block's 256 nodes' features by dinv (fp16 in, fp16 out)
    int base = b * 256 * 12;
    #pragma unroll
    for (int k = 0; k < 12; k++) {
        int idx = t + k * 256;               // 0..3071
        int node = b * 256 + (idx / 12);
        if (node < NN) {
            float d = sdinv[idx / 12];
            uint4 v4 = g_xTh[base + idx];
            __half2* h = (__half2*)&v4;
            #pragma unroll
            for (int j = 0; j < 4; j++) {
                float2 f = __half22float2(h[j]);
                h[j] = __floats2half2_rn(f.x * d, f.y * d);
            }
            g_xTh[base + idx] = v4;
        }
    }
}

// ---------------- kernel 5: fill CSR records {row, ew}, 2 edges/thread ----
__global__ void k_fill(const int* __restrict__ ei, const float* __restrict__ ew) {
    int e = (blockIdx.x * blockDim.x + threadIdx.x) * 2;
    if (e >= EE) return;
    int2 rows = *(const int2*)&ei[e];
    int2 cols = *(const int2*)&ei[EE + e];
    float2 w = *(const float2*)&ew[e];
    int p0 = atomicAdd(&g_cur[cols.x], 1);
    g_rec[p0] = make_int2(rows.x, __float_as_int(w.x));
    int p1 = atomicAdd(&g_cur[cols.y], 1);
    g_rec[p1] = make_int2(rows.y, __float_as_int(w.y));
}

// ---------------- fp16 chunk FMA into fp32 acc ----------------------------
__device__ __forceinline__ void h8_fma(float acc[8], uint4 v, float c) {
    const __half2* h = (const __half2*)&v;
    #pragma unroll
    for (int i = 0; i < 4; i++) {
        float2 f = __half22float2(h[i]);
        acc[2 * i]     = fmaf(c, f.x, acc[2 * i]);
        acc[2 * i + 1] = fmaf(c, f.y, acc[2 * i + 1]);
    }
}

// ---------------- kernel 6: FUSED gather + collapsed GRU + BN stats -------
__global__ void __launch_bounds__(256) k_fused() {
    __shared__ float bsum[64], bsq[64];
    if (threadIdx.x < 64) { bsum[threadIdx.x] = 0.f; bsq[threadIdx.x] = 0.f; }
    __syncthreads();

    int lane = threadIdx.x & 31;
    int warp = threadIdx.x >> 5;
    bool act = lane < 24;
    int grp = (lane >= 12 && lane < 24) ? 1 : 0;
    int sub = act ? (lane - grp * 12) : 0;

    float2 az[8], ah[8];
    #pragma unroll
    for (int i = 0; i < 8; i++) {
        az[i] = *(const float2*)&g_Az[i * 64 + 2 * lane];
        ah[i] = *(const float2*)&g_Ah[i * 64 + 2 * lane];
    }
    float2 cz = *(const float2*)&g_cz[2 * lane];
    float2 ch = *(const float2*)&g_ch[2 * lane];

    float psx = 0.f, psy = 0.f, pqx = 0.f, pqy = 0.f;

    for (int n = blockIdx.x * 8 + warp; n < NN; n += FUSED_BLOCKS * 8) {
        float2 dc = g_degcnt[n];
        float dn = rsqrtf(dc.x);
        int cnt = (int)dc.y;
        int start = g_start[n];

        float acc[8] = {0.f, 0.f, 0.f, 0.f, 0.f, 0.f, 0.f, 0.f};
        if (lane < 12)                       // self term: dinv*y[n] (y already dinv-scaled)
            h8_fma(acc, g_xTh[n * 12 + sub], 1.0f);

        int e = start, end = start + cnt;
        for (; e + 8 <= end; e += 8) {
            if (act) {
                int2 r0 = g_rec[e + grp];
                int2 r1 = g_rec[e + 2 + grp];
                int2 r2 = g_rec[e + 4 + grp];
                int2 r3 = g_rec[e + 6 + grp];
                uint4 v0 = g_xTh[r0.x * 12 + sub];
                uint4 v1 = g_xTh[r1.x * 12 + sub];
                uint4 v2 = g_xTh[r2.x * 12 + sub];
                uint4 v3 = g_xTh[r3.x * 12 + sub];
                h8_fma(acc, v0, __int_as_float(r0.y));
                h8_fma(acc, v1, __int_as_float(r1.y));
                h8_fma(acc, v2, __int_as_float(r2.y));
                h8_fma(acc, v3, __int_as_float(r3.y));
            }
        }
        for (; e < end; e += 2) {
            if (act && e + grp < end) {
                int2 r0 = g_rec[e + grp];
                uint4 v0 = g_xTh[r0.x * 12 + sub];
                h8_fma(acc, v0, __int_as_float(r0.y));
            }
        }
        #pragma unroll
        for (int i = 0; i < 8; i++) {
            acc[i] += __shfl_down_sync(0xffffffffu, acc[i], 12);
            acc[i] *= dn;                    // dinv[col] factored once
        }

        // collapsed GRU: lane owns hidden dims 2*lane, 2*lane+1
        float hx = 0.f, hy = 0.f;
        #pragma unroll
        for (int p = 0; p < PP; p++) {
            float u[8];
            #pragma unroll
            for (int i = 0; i < 8; i++)
                u[i] = __shfl_sync(0xffffffffu, acc[i], p);
            float ax = cz.x, ay = cz.y, bx = ch.x, by = ch.y;   // ax,ay pre-halved
            #pragma unroll
            for (int i = 0; i < 8; i++) {
                ax = fmaf(u[i], az[i].x, ax);  ay = fmaf(u[i], az[i].y, ay);
                bx = fmaf(u[i], ah[i].x, bx);  by = fmaf(u[i], ah[i].y, by);
            }
            float zx = fmaf(-0.5f, tanha(ax), 0.5f);   // 1 - sigmoid(2*ax)
            float zy = fmaf(-0.5f, tanha(ay), 0.5f);
            float tx = tanha(bx);
            float ty = tanha(by);
            float pw = g_probs[p];
            hx = fmaf(pw * zx, tx, hx);
            hy = fmaf(pw * zy, ty, hy);
        }
        hx = fmaxf(hx, 0.f);
        hy = fmaxf(hy, 0.f);
        *(float2*)&g_H[n * 64 + 2 * lane] = make_float2(hx, hy);
        psx += hx; pqx += hx * hx;
        psy += hy; pqy += hy * hy;
    }

    atomicAdd(&bsum[2 * lane],     psx);
    atomicAdd(&bsum[2 * lane + 1], psy);
    atomicAdd(&bsq[2 * lane],      pqx);
    atomicAdd(&bsq[2 * lane + 1],  pqy);
    __syncthreads();
    if (threadIdx.x < 64) {
        atomicAdd(&g_sums[threadIdx.x],  bsum[threadIdx.x]);
        atomicAdd(&g_sumsq[threadIdx.x], bsq[threadIdx.x]);
    }
}

// ---------------- kernel 7: BN-fold + out = relu(H) @ W_eff + b_eff -------
__global__ void __launch_bounds__(256) k_out(const float* __restrict__ gamma,
                                             const float* __restrict__ beta,
                                             float* __restrict__ out) {
    __shared__ float sW[64 * 96];
    __shared__ float sb[96];
    __shared__ float ss[64], st[64];
    int tid = threadIdx.x;
    if (tid < 64) {
        float mean = g_sums[tid] * (1.0f / (float)NN);
        float var  = g_sumsq[tid] * (1.0f / (float)NN) - mean * mean;
        float sc = gamma[tid] * rsqrtf(var + 1e-5f);
        ss[tid] = sc;
        st[tid] = beta[tid] - mean * sc;
    }
    __syncthreads();
    for (int idx = tid; idx < 64 * 96; idx += 256)
        sW[idx] = ss[idx / 96] * g_Wc[idx];
    if (tid < 96) {
        float s = g_bc[tid];
        for (int k = 0; k < 64; k++) s += st[k] * g_Wc[k * 96 + tid];
        sb[tid] = s;
    }
    __syncthreads();

    int lane = tid & 31;
    int warp = tid >> 5;
    for (int n = blockIdx.x * 8 + warp; n < NN; n += OUT_BLOCKS * 8) {
        float2 h2 = *(const float2*)&g_H[n * 64 + 2 * lane];
        float a0 = sb[lane], a1 = sb[lane + 32], a2 = sb[lane + 64];
        #pragma unroll
        for (int i = 0; i < 64; i++) {
            float hv = __shfl_sync(0xffffffffu, (i & 1) ? h2.y : h2.x, i >> 1);
            const float* wr = &sW[i * 96];
            a0 = fmaf(hv, wr[lane],      a0);
            a1 = fmaf(hv, wr[lane + 32], a1);
            a2 = fmaf(hv, wr[lane + 64], a2);
        }
        float* ob = out + n * 96;
        ob[lane] = a0; ob[lane + 32] = a1; ob[lane + 64] = a2;
    }
}

// ---------------- launch ---------------------------------------------------
extern "C" void kernel_launch(void* const* d_in, const int* in_sizes, int n_in,
                              void* d_out, int out_size) {
    const float* x      = (const float*)d_in[0];
    const int*   ei     = (const int*)  d_in[1];
    const float* ew     = (const float*)d_in[2];
    const float* att    = (const float*)d_in[3];
    const float* conv_w = (const float*)d_in[4];
    const float* conv_b = (const float*)d_in[5];
    const float* lin_w  = (const float*)d_in[6];
    const float* lin_b  = (const float*)d_in[7];
    const float* gamma  = (const float*)d_in[8];
    const float* beta   = (const float*)d_in[9];
    const float* W1 = (const float*)d_in[10]; const float* b1 = (const float*)d_in[11];
    const float* W2 = (const float*)d_in[12]; const float* b2 = (const float*)d_in[13];
    const float* W3 = (const float*)d_in[14]; const float* b3 = (const float*)d_in[15];
    const float* W4 = (const float*)d_in[16]; const float* b4 = (const float*)d_in[17];
    const float* W5 = (const float*)d_in[18]; const float* b5 = (const float*)d_in[19];
    float* out = (float*)d_out;

    k_pre0<<<PREPX_BLOCKS + 1, 256>>>(x, att, conv_w, conv_b, lin_w, lin_b,
                                      W1, b1, W2, b2, W3, b3, W4, b4, W5, b5);
    k_count<<<(EE / 4 + 255) / 256, 256>>>(ei, ew);
    k_scanA<<<SCAN_BLOCKS, 256>>>();
    k_scanB<<<SCAN_BLOCKS, 256>>>();
    k_fill<<<(EE / 2 + 255) / 256, 256>>>(ei, ew);
    k_fused<<<FUSED_BLOCKS, 256>>>();
    k_out<<<OUT_BLOCKS, 256>>>(gamma, beta, out);
}

// round 5
// speedup vs baseline: 1.8109x; 1.0283x over previous
#include <cuda_runtime.h>
#include <cuda_fp16.h>

#define NN 50000
#define EE 800000
#define PP 12
#define SCAN_BLOCKS 196      // ceil(NN/256)
#define PREPX_BLOCKS 1563    // ceil(NN/32)
#define SF_BLOCKS 592        // 148 * 4, must be co-resident (software barrier)
#define FUSED_BLOCKS 888     // 148 * 6
#define OUT_BLOCKS 888

// ---------------- scratch (device globals; no allocation) ----------------
__device__ float2 g_degcnt[NN];          // .x = deg(+1 self), .y = in-edge count
__device__ float  g_dinv[NN];
__device__ int    g_start[NN];
__device__ int    g_cur[NN];
__device__ int    g_base;                // atomic CSR base allocator
__device__ volatile int g_barrier;       // software grid barrier
__device__ int2   g_rec[EE];             // CSR-ordered {row, coeff = dinv[row]*ew}
__device__ uint4  g_xTh[NN * 12];        // node-major fp16 features (unscaled)
__device__ float  g_H[NN * 64];          // relu(H_accum)
__device__ float  g_sums[64];
__device__ float  g_sumsq[64];
__device__ float  g_Az[8 * 64], g_Ah[8 * 64];   // Az, cz pre-folded by 0.5
__device__ float  g_cz[64], g_ch[64];
__device__ float  g_probs[PP];
__device__ float  g_Wc[64 * 96], g_bc[96];

__device__ __forceinline__ float tanha(float x) {
    float r; asm("tanh.approx.f32 %0, %1;" : "=f"(r) : "f"(x)); return r;
}

// ---------------- kernel 1: prepx (+init) blocks 0..1562, pre1 on 1563 ----
__global__ void __launch_bounds__(256) k_pre0(
        const float* __restrict__ x,
        const float* __restrict__ att,
        const float* __restrict__ conv_w, const float* __restrict__ conv_b,
        const float* __restrict__ lin_w,  const float* __restrict__ lin_b,
        const float* __restrict__ W1, const float* __restrict__ b1,
        const float* __restrict__ W2, const float* __restrict__ b2,
        const float* __restrict__ W3, const float* __restrict__ b3,
        const float* __restrict__ W4, const float* __restrict__ b4,
        const float* __restrict__ W5, const float* __restrict__ b5) {
    __shared__ __align__(16) char sm[14592];
    int tid = threadIdx.x;

    if (blockIdx.x < PREPX_BLOCKS) {
        float* s = (float*)sm;                      // 32*96 floats
        int blockNode = blockIdx.x * 32;
        int gi = blockIdx.x * 256 + tid;
        if (gi < NN) g_degcnt[gi] = make_float2(1.0f, 0.0f);
        int lim = (NN - blockNode) * 96;
        for (int i = tid; i < 32 * 96; i += 256)
            s[i] = (i < lim) ? x[blockNode * 96 + i] : 0.f;
        __syncthreads();
        #pragma unroll
        for (int k = 0; k < 2; k++) {
            int o = tid + k * 256;                  // 0..383 = 32 nodes * 12 chunks
            if (o < 32 * 12) {
                int ln = o / 12, p = o - ln * 12;
                int n = blockNode + ln;
                if (n < NN) {
                    __align__(16) __half hv[8];
                    #pragma unroll
                    for (int f = 0; f < 8; f++)
                        hv[f] = __float2half_rn(s[ln * 96 + f * 12 + p]);
                    g_xTh[n * 12 + p] = *(const uint4*)hv;
                }
            }
        }
        return;
    }

    // ---- pre1: fold all the small linear algebra ----
    float* sT1 = (float*)sm;           // 2048
    float* sT2 = sT1 + 2048;           // 1024
    float* sT3 = sT2 + 1024;           // 512
    float* sb  = sT3 + 512;            // 56

    if (tid == 0) {
        float m = -1e30f;
        for (int i = 0; i < PP; i++) m = fmaxf(m, att[i]);
        float e[PP], s = 0.f;
        for (int i = 0; i < PP; i++) { e[i] = __expf(att[i] - m); s += e[i]; }
        for (int i = 0; i < PP; i++) g_probs[i] = e[i] / s;
    }
    for (int idx = tid; idx < 8 * 64; idx += 256) {
        int i = idx >> 6, j = idx & 63;
        float az = 0.f, ah = 0.f;
        for (int k = 0; k < 64; k++) {
            az += conv_w[0 * 512 + i * 64 + k] * lin_w[0 * 8192 + k * 64 + j];
            ah += conv_w[2 * 512 + i * 64 + k] * lin_w[2 * 8192 + k * 64 + j];
        }
        g_Az[idx] = 0.5f * az; g_Ah[idx] = ah;
    }
    for (int j = tid; j < 64; j += 256) {
        float cz = lin_b[0 * 64 + j], ch = lin_b[2 * 64 + j];
        for (int k = 0; k < 64; k++) {
            cz += conv_b[0 * 64 + k] * lin_w[0 * 8192 + k * 64 + j];
            ch += conv_b[2 * 64 + k] * lin_w[2 * 8192 + k * 64 + j];
        }
        g_cz[j] = 0.5f * cz; g_ch[j] = ch;
        g_sums[j] = 0.f; g_sumsq[j] = 0.f;
    }
    for (int idx = tid; idx < 64 * 32; idx += 256) {
        int i = idx >> 5, j = idx & 31; float s = 0.f;
        for (int k = 0; k < 64; k++) s += W1[i * 64 + k] * W2[k * 32 + j];
        sT1[idx] = s;
    }
    if (tid < 32) { float s = b2[tid]; for (int k = 0; k < 64; k++) s += b1[k] * W2[k * 32 + tid]; sb[tid] = s; }
    __syncthreads();
    for (int idx = tid; idx < 64 * 16; idx += 256) {
        int i = idx >> 4, j = idx & 15; float s = 0.f;
        for (int k = 0; k < 32; k++) s += sT1[i * 32 + k] * W3[k * 16 + j];
        sT2[idx] = s;
    }
    if (tid < 16) { float s = b3[tid]; for (int k = 0; k < 32; k++) s += sb[k] * W3[k * 16 + tid]; sb[32 + tid] = s; }
    __syncthreads();
    for (int idx = tid; idx < 64 * 8; idx += 256) {
        int i = idx >> 3, j = idx & 7; float s = 0.f;
        for (int k = 0; k < 16; k++) s += sT2[i * 16 + k] * W4[k * 8 + j];
        sT3[idx] = s;
    }
    if (tid < 8) { float s = b4[tid]; for (int k = 0; k < 16; k++) s += sb[32 + k] * W4[k * 8 + tid]; sb[48 + tid] = s; }
    __syncthreads();
    for (int idx = tid; idx < 64 * 96; idx += 256) {
        int i = idx / 96, j = idx - i * 96; float s = 0.f;
        for (int k = 0; k < 8; k++) s += sT3[i * 8 + k] * W5[k * 96 + j];
        g_Wc[idx] = s;
    }
    for (int j = tid; j < 96; j += 256) {
        float s = b5[j];
        for (int k = 0; k < 8; k++) s += sb[48 + k] * W5[k * 96 + j];
        g_bc[j] = s;
    }
}

// ---------------- kernel 2: degree + count, 4 edges/thread ----------------
__global__ void k_count(const int* __restrict__ ei, const float* __restrict__ ew) {
    if (blockIdx.x == 0 && threadIdx.x == 0) { g_base = 0; *(int*)&g_barrier = 0; }
    int e = (blockIdx.x * blockDim.x + threadIdx.x) * 4;
    if (e < EE) {
        int4 cols = *(const int4*)&ei[EE + e];
        float4 w = *(const float4*)&ew[e];
        asm volatile("red.global.add.v2.f32 [%0], {%1, %2};"
                     :: "l"(&g_degcnt[cols.x]), "f"(w.x), "f"(1.0f) : "memory");
        asm volatile("red.global.add.v2.f32 [%0], {%1, %2};"
                     :: "l"(&g_degcnt[cols.y]), "f"(w.y), "f"(1.0f) : "memory");
        asm volatile("red.global.add.v2.f32 [%0], {%1, %2};"
                     :: "l"(&g_degcnt[cols.z]), "f"(w.z), "f"(1.0f) : "memory");
        asm volatile("red.global.add.v2.f32 [%0], {%1, %2};"
                     :: "l"(&g_degcnt[cols.w]), "f"(w.w), "f"(1.0f) : "memory");
    }
}

// ---------------- kernel 3: scan (atomic base) + barrier + fill -----------
__global__ void __launch_bounds__(256) k_scanfill(const int* __restrict__ ei,
                                                  const float* __restrict__ ew) {
    __shared__ int s[256];
    __shared__ int sbase;
    int t = threadIdx.x, b = blockIdx.x;

    // ---- phase A: per-block scan of counts, base via atomicAdd ----
    if (b < SCAN_BLOCKS) {
        int i = b * 256 + t;
        int c = 0;
        if (i < NN) {
            float2 dc = g_degcnt[i];
            g_dinv[i] = rsqrtf(dc.x);
            c = (int)dc.y;
        }
        s[t] = c;
        __syncthreads();
        for (int off = 1; off < 256; off <<= 1) {
            int u = (t >= off) ? s[t - off] : 0;
            __syncthreads();
            s[t] += u;
            __syncthreads();
        }
        if (t == 255) sbase = atomicAdd(&g_base, s[255]);
        __syncthreads();
        if (i < NN) {
            int ex = sbase + s[t] - c;
            g_start[i] = ex;
            g_cur[i] = ex;
        }
    }

    // ---- device-wide barrier (all SF_BLOCKS co-resident) ----
    __threadfence();
    __syncthreads();
    if (t == 0) {
        atomicAdd((int*)&g_barrier, 1);
        while (g_barrier < SF_BLOCKS) { }
    }
    __syncthreads();
    __threadfence();

    // ---- phase B: fill CSR records {row, dinv[row]*ew}, 2 edges/iter ----
    int stride = SF_BLOCKS * 256 * 2;
    for (int e = (b * 256 + t) * 2; e < EE; e += stride) {
        int2 rows = *(const int2*)&ei[e];
        int2 cols = *(const int2*)&ei[EE + e];
        float2 w = *(const float2*)&ew[e];
        float c0 = g_dinv[rows.x] * w.x;
        float c1 = g_dinv[rows.y] * w.y;
        int p0 = atomicAdd(&g_cur[cols.x], 1);
        g_rec[p0] = make_int2(rows.x, __float_as_int(c0));
        int p1 = atomicAdd(&g_cur[cols.y], 1);
        g_rec[p1] = make_int2(rows.y, __float_as_int(c1));
    }
}

// ---------------- fp16 chunk FMA into fp32 acc ----------------------------
__device__ __forceinline__ void h8_fma(float acc[8], uint4 v, float c) {
    const __half2* h = (const __half2*)&v;
    #pragma unroll
    for (int i = 0; i < 4; i++) {
        float2 f = __half22float2(h[i]);
        acc[2 * i]     = fmaf(c, f.x, acc[2 * i]);
        acc[2 * i + 1] = fmaf(c, f.y, acc[2 * i + 1]);
    }
}

// ---------------- kernel 4: FUSED gather + collapsed GRU + BN stats -------
__global__ void __launch_bounds__(256) k_fused() {
    __shared__ float bsum[64], bsq[64];
    if (threadIdx.x < 64) { bsum[threadIdx.x] = 0.f; bsq[threadIdx.x] = 0.f; }
    __syncthreads();

    int lane = threadIdx.x & 31;
    int warp = threadIdx.x >> 5;
    bool act = lane < 24;
    int grp = (lane >= 12 && lane < 24) ? 1 : 0;
    int sub = act ? (lane - grp * 12) : 0;

    float2 az[8], ah[8];
    #pragma unroll
    for (int i = 0; i < 8; i++) {
        az[i] = *(const float2*)&g_Az[i * 64 + 2 * lane];
        ah[i] = *(const float2*)&g_Ah[i * 64 + 2 * lane];
    }
    float2 cz = *(const float2*)&g_cz[2 * lane];
    float2 ch = *(const float2*)&g_ch[2 * lane];

    float psx = 0.f, psy = 0.f, pqx = 0.f, pqy = 0.f;

    for (int n = blockIdx.x * 8 + warp; n < NN; n += FUSED_BLOCKS * 8) {
        float2 dc = g_degcnt[n];
        float dn = rsqrtf(dc.x);
        int cnt = (int)dc.y;
        int start = g_start[n];

        float acc[8] = {0.f, 0.f, 0.f, 0.f, 0.f, 0.f, 0.f, 0.f};
        if (lane < 12)                       // self term: coeff dn (plus dn at end -> dn^2)
            h8_fma(acc, g_xTh[n * 12 + sub], dn);

        int e = start, end = start + cnt;
        for (; e + 8 <= end; e += 8) {
            if (act) {
                int2 r0 = g_rec[e + grp];
                int2 r1 = g_rec[e + 2 + grp];
                int2 r2 = g_rec[e + 4 + grp];
                int2 r3 = g_rec[e + 6 + grp];
                uint4 v0 = g_xTh[r0.x * 12 + sub];
                uint4 v1 = g_xTh[r1.x * 12 + sub];
                uint4 v2 = g_xTh[r2.x * 12 + sub];
                uint4 v3 = g_xTh[r3.x * 12 + sub];
                h8_fma(acc, v0, __int_as_float(r0.y));
                h8_fma(acc, v1, __int_as_float(r1.y));
                h8_fma(acc, v2, __int_as_float(r2.y));
                h8_fma(acc, v3, __int_as_float(r3.y));
            }
        }
        for (; e < end; e += 2) {
            if (act && e + grp < end) {
                int2 r0 = g_rec[e + grp];
                uint4 v0 = g_xTh[r0.x * 12 + sub];
                h8_fma(acc, v0, __int_as_float(r0.y));
            }
        }
        #pragma unroll
        for (int i = 0; i < 8; i++) {
            acc[i] += __shfl_down_sync(0xffffffffu, acc[i], 12);
            acc[i] *= dn;                    // dinv[col]
        }

        // collapsed GRU: lane owns hidden dims 2*lane, 2*lane+1
        float hx = 0.f, hy = 0.f;
        #pragma unroll
        for (int p = 0; p < PP; p++) {
            float u[8];
            #pragma unroll
            for (int i = 0; i < 8; i++)
                u[i] = __shfl_sync(0xffffffffu, acc[i], p);
            float ax = cz.x, ay = cz.y, bx = ch.x, by = ch.y;   // ax,ay pre-halved
            #pragma unroll
            for (int i = 0; i < 8; i++) {
                ax = fmaf(u[i], az[i].x, ax);  ay = fmaf(u[i], az[i].y, ay);
                bx = fmaf(u[i], ah[i].x, bx);  by = fmaf(u[i], ah[i].y, by);
            }
            float zx = fmaf(-0.5f, tanha(ax), 0.5f);   // 1 - sigmoid(2*ax)
            float zy = fmaf(-0.5f, tanha(ay), 0.5f);
            float tx = tanha(bx);
            float ty = tanha(by);
            float pw = g_probs[p];
            hx = fmaf(pw * zx, tx, hx);
            hy = fmaf(pw * zy, ty, hy);
        }
        hx = fmaxf(hx, 0.f);
        hy = fmaxf(hy, 0.f);
        *(float2*)&g_H[n * 64 + 2 * lane] = make_float2(hx, hy);
        psx += hx; pqx += hx * hx;
        psy += hy; pqy += hy * hy;
    }

    atomicAdd(&bsum[2 * lane],     psx);
    atomicAdd(&bsum[2 * lane + 1], psy);
    atomicAdd(&bsq[2 * lane],      pqx);
    atomicAdd(&bsq[2 * lane + 1],  pqy);
    __syncthreads();
    if (threadIdx.x < 64) {
        atomicAdd(&g_sums[threadIdx.x],  bsum[threadIdx.x]);
        atomicAdd(&g_sumsq[threadIdx.x], bsq[threadIdx.x]);
    }
}

// ---------------- kernel 5: BN-fold + out = relu(H) @ W_eff + b_eff -------
__global__ void __launch_bounds__(256) k_out(const float* __restrict__ gamma,
                                             const float* __restrict__ beta,
                                             float* __restrict__ out) {
    __shared__ float sW[64 * 96];
    __shared__ float sb[96];
    __shared__ float ss[64], st[64];
    int tid = threadIdx.x;
    if (tid < 64) {
        float mean = g_sums[tid] * (1.0f / (float)NN);
        float var  = g_sumsq[tid] * (1.0f / (float)NN) - mean * mean;
        float sc = gamma[tid] * rsqrtf(var + 1e-5f);
        ss[tid] = sc;
        st[tid] = beta[tid] - mean * sc;
    }
    __syncthreads();
    for (int idx = tid; idx < 64 * 96; idx += 256)
        sW[idx] = ss[idx / 96] * g_Wc[idx];
    if (tid < 96) {
        float s = g_bc[tid];
        for (int k = 0; k < 64; k++) s += st[k] * g_Wc[k * 96 + tid];
        sb[tid] = s;
    }
    __syncthreads();

    int lane = tid & 31;
    int warp = tid >> 5;
    for (int n = blockIdx.x * 8 + warp; n < NN; n += OUT_BLOCKS * 8) {
        float2 h2 = *(const float2*)&g_H[n * 64 + 2 * lane];
        float a0 = sb[lane], a1 = sb[lane + 32], a2 = sb[lane + 64];
        #pragma unroll
        for (int i = 0; i < 64; i++) {
            float hv = __shfl_sync(0xffffffffu, (i & 1) ? h2.y : h2.x, i >> 1);
            const float* wr = &sW[i * 96];
            a0 = fmaf(hv, wr[lane],      a0);
            a1 = fmaf(hv, wr[lane + 32], a1);
            a2 = fmaf(hv, wr[lane + 64], a2);
        }
        float* ob = out + n * 96;
        ob[lane] = a0; ob[lane + 32] = a1; ob[lane + 64] = a2;
    }
}

// ---------------- launch ---------------------------------------------------
extern "C" void kernel_launch(void* const* d_in, const int* in_sizes, int n_in,
                              void* d_out, int out_size) {
    const float* x      = (const float*)d_in[0];
    const int*   ei     = (const int*)  d_in[1];
    const float* ew     = (const float*)d_in[2];
    const float* att    = (const float*)d_in[3];
    const float* conv_w = (const float*)d_in[4];
    const float* conv_b = (const float*)d_in[5];
    const float* lin_w  = (const float*)d_in[6];
    const float* lin_b  = (const float*)d_in[7];
    const float* gamma  = (const float*)d_in[8];
    const float* beta   = (const float*)d_in[9];
    const float* W1 = (const float*)d_in[10]; const float* b1 = (const float*)d_in[11];
    const float* W2 = (const float*)d_in[12]; const float* b2 = (const float*)d_in[13];
    const float* W3 = (const float*)d_in[14]; const float* b3 = (const float*)d_in[15];
    const float* W4 = (const float*)d_in[16]; const float* b4 = (const float*)d_in[17];
    const float* W5 = (const float*)d_in[18]; const float* b5 = (const float*)d_in[19];
    float* out = (float*)d_out;

    k_pre0<<<PREPX_BLOCKS + 1, 256>>>(x, att, conv_w, conv_b, lin_w, lin_b,
                                      W1, b1, W2, b2, W3, b3, W4, b4, W5, b5);
    k_count<<<(EE / 4 + 255) / 256, 256>>>(ei, ew);
    k_scanfill<<<SF_BLOCKS, 256>>>(ei, ew);
    k_fused<<<FUSED_BLOCKS, 256>>>();
    k_out<<<OUT_BLOCKS, 256>>>(gamma, beta, out);
}

// round 6
// speedup vs baseline: 1.8138x; 1.0016x over previous
#include <cuda_runtime.h>

#define NN 50000
#define EE 800000
#define PP 12
#define SCAN_BLOCKS 196      // ceil(NN/256)
#define PREPX_BLOCKS 1563    // ceil(NN/32)
#define SF_BLOCKS 592        // 148 * 4, must be co-resident (software barrier)
#define FUSED_BLOCKS 888     // 148 * 6
#define OUT_BLOCKS 888

typedef unsigned long long u64;

// ---------------- scratch (device globals; no allocation) ----------------
__device__ float2 g_degcnt[NN];          // .x = deg(+1 self), .y = in-edge count
__device__ float  g_dinv[NN];
__device__ int    g_start[NN];
__device__ int    g_cur[NN];
__device__ int    g_base;                // atomic CSR base allocator
__device__ volatile int g_barrier;       // software grid barrier
__device__ int2   g_rec[EE];             // CSR-ordered {row, coeff = dinv[row]*ew}
__device__ ulonglong2 g_xT32[NN * 24];   // fp32 features: [n][h][sub] float4 (h=f/4, sub=period)
__device__ float  g_H[NN * 64];          // relu(H_accum)
__device__ float  g_sums[64];
__device__ float  g_sumsq[64];
__device__ float  g_Az[8 * 64], g_Ah[8 * 64];   // Az, cz pre-folded by 0.5
__device__ float  g_cz[64], g_ch[64];
__device__ float  g_probs[PP];
__device__ float  g_Wc[64 * 96], g_bc[96];

__device__ __forceinline__ float tanha(float x) {
    float r; asm("tanh.approx.f32 %0, %1;" : "=f"(r) : "f"(x)); return r;
}
__device__ __forceinline__ u64 pk(float x, float y) {
    u64 r; asm("mov.b64 %0, {%1, %2};" : "=l"(r) : "f"(x), "f"(y)); return r;
}
__device__ __forceinline__ void upk(u64 v, float& x, float& y) {
    asm("mov.b64 {%0, %1}, %2;" : "=f"(x), "=f"(y) : "l"(v));
}
__device__ __forceinline__ u64 ffma2(u64 a, u64 b, u64 c) {
    u64 d; asm("fma.rn.f32x2 %0, %1, %2, %3;" : "=l"(d) : "l"(a), "l"(b), "l"(c)); return d;
}
__device__ __forceinline__ u64 fadd2(u64 a, u64 b) {
    u64 d; asm("add.rn.f32x2 %0, %1, %2;" : "=l"(d) : "l"(a), "l"(b)); return d;
}
__device__ __forceinline__ u64 fmul2(u64 a, u64 b) {
    u64 d; asm("mul.rn.f32x2 %0, %1, %2;" : "=l"(d) : "l"(a), "l"(b)); return d;
}

// ---------------- kernel 1: prepx (+init) blocks 0..1562, pre1 on 1563 ----
__global__ void __launch_bounds__(256) k_pre0(
        const float* __restrict__ x,
        const float* __restrict__ att,
        const float* __restrict__ conv_w, const float* __restrict__ conv_b,
        const float* __restrict__ lin_w,  const float* __restrict__ lin_b,
        const float* __restrict__ W1, const float* __restrict__ b1,
        const float* __restrict__ W2, const float* __restrict__ b2,
        const float* __restrict__ W3, const float* __restrict__ b3,
        const float* __restrict__ W4, const float* __restrict__ b4,
        const float* __restrict__ W5, const float* __restrict__ b5) {
    __shared__ __align__(16) char sm[14592];
    int tid = threadIdx.x;

    if (blockIdx.x < PREPX_BLOCKS) {
        float* s = (float*)sm;                      // 32*96 floats
        int blockNode = blockIdx.x * 32;
        int gi = blockIdx.x * 256 + tid;
        if (gi < NN) g_degcnt[gi] = make_float2(1.0f, 0.0f);
        int lim = (NN - blockNode) * 96;
        for (int i = tid; i < 32 * 96; i += 256)
            s[i] = (i < lim) ? x[blockNode * 96 + i] : 0.f;
        __syncthreads();
        #pragma unroll
        for (int k = 0; k < 3; k++) {
            int o = tid + k * 256;                  // 0..767 = 32 nodes * 24 float4
            if (o < 32 * 24) {
                int ln = o / 24, l = o - ln * 24;
                int n = blockNode + ln;
                if (n < NN) {
                    int h = l / 12, sub = l - h * 12;
                    float4 v;
                    v.x = s[ln * 96 + (h * 4 + 0) * 12 + sub];
                    v.y = s[ln * 96 + (h * 4 + 1) * 12 + sub];
                    v.z = s[ln * 96 + (h * 4 + 2) * 12 + sub];
                    v.w = s[ln * 96 + (h * 4 + 3) * 12 + sub];
                    *(float4*)&g_xT32[n * 24 + h * 12 + sub] = v;
                }
            }
        }
        return;
    }

    // ---- pre1: fold all the small linear algebra ----
    float* sT1 = (float*)sm;           // 2048
    float* sT2 = sT1 + 2048;           // 1024
    float* sT3 = sT2 + 1024;           // 512
    float* sb  = sT3 + 512;            // 56

    if (tid == 0) {
        float m = -1e30f;
        for (int i = 0; i < PP; i++) m = fmaxf(m, att[i]);
        float e[PP], s = 0.f;
        for (int i = 0; i < PP; i++) { e[i] = __expf(att[i] - m); s += e[i]; }
        for (int i = 0; i < PP; i++) g_probs[i] = e[i] / s;
    }
    for (int idx = tid; idx < 8 * 64; idx += 256) {
        int i = idx >> 6, j = idx & 63;
        float az = 0.f, ah = 0.f;
        for (int k = 0; k < 64; k++) {
            az += conv_w[0 * 512 + i * 64 + k] * lin_w[0 * 8192 + k * 64 + j];
            ah += conv_w[2 * 512 + i * 64 + k] * lin_w[2 * 8192 + k * 64 + j];
        }
        g_Az[idx] = 0.5f * az; g_Ah[idx] = ah;
    }
    for (int j = tid; j < 64; j += 256) {
        float cz = lin_b[0 * 64 + j], ch = lin_b[2 * 64 + j];
        for (int k = 0; k < 64; k++) {
            cz += conv_b[0 * 64 + k] * lin_w[0 * 8192 + k * 64 + j];
            ch += conv_b[2 * 64 + k] * lin_w[2 * 8192 + k * 64 + j];
        }
        g_cz[j] = 0.5f * cz; g_ch[j] = ch;
        g_sums[j] = 0.f; g_sumsq[j] = 0.f;
    }
    for (int idx = tid; idx < 64 * 32; idx += 256) {
        int i = idx >> 5, j = idx & 31; float s = 0.f;
        for (int k = 0; k < 64; k++) s += W1[i * 64 + k] * W2[k * 32 + j];
        sT1[idx] = s;
    }
    if (tid < 32) { float s = b2[tid]; for (int k = 0; k < 64; k++) s += b1[k] * W2[k * 32 + tid]; sb[tid] = s; }
    __syncthreads();
    for (int idx = tid; idx < 64 * 16; idx += 256) {
        int i = idx >> 4, j = idx & 15; float s = 0.f;
        for (int k = 0; k < 32; k++) s += sT1[i * 32 + k] * W3[k * 16 + j];
        sT2[idx] = s;
    }
    if (tid < 16) { float s = b3[tid]; for (int k = 0; k < 32; k++) s += sb[k] * W3[k * 16 + tid]; sb[32 + tid] = s; }
    __syncthreads();
    for (int idx = tid; idx < 64 * 8; idx += 256) {
        int i = idx >> 3, j = idx & 7; float s = 0.f;
        for (int k = 0; k < 16; k++) s += sT2[i * 16 + k] * W4[k * 8 + j];
        sT3[idx] = s;
    }
    if (tid < 8) { float s = b4[tid]; for (int k = 0; k < 16; k++) s += sb[32 + k] * W4[k * 8 + tid]; sb[48 + tid] = s; }
    __syncthreads();
    for (int idx = tid; idx < 64 * 96; idx += 256) {
        int i = idx / 96, j = idx - i * 96; float s = 0.f;
        for (int k = 0; k < 8; k++) s += sT3[i * 8 + k] * W5[k * 96 + j];
        g_Wc[idx] = s;
    }
    for (int j = tid; j < 96; j += 256) {
        float s = b5[j];
        for (int k = 0; k < 8; k++) s += sb[48 + k] * W5[k * 96 + j];
        g_bc[j] = s;
    }
}

// ---------------- kernel 2: degree + count, 4 edges/thread ----------------
__global__ void k_count(const int* __restrict__ ei, const float* __restrict__ ew) {
    if (blockIdx.x == 0 && threadIdx.x == 0) { g_base = 0; *(int*)&g_barrier = 0; }
    int e = (blockIdx.x * blockDim.x + threadIdx.x) * 4;
    if (e < EE) {
        int4 cols = *(const int4*)&ei[EE + e];
        float4 w = *(const float4*)&ew[e];
        asm volatile("red.global.add.v2.f32 [%0], {%1, %2};"
                     :: "l"(&g_degcnt[cols.x]), "f"(w.x), "f"(1.0f) : "memory");
        asm volatile("red.global.add.v2.f32 [%0], {%1, %2};"
                     :: "l"(&g_degcnt[cols.y]), "f"(w.y), "f"(1.0f) : "memory");
        asm volatile("red.global.add.v2.f32 [%0], {%1, %2};"
                     :: "l"(&g_degcnt[cols.z]), "f"(w.z), "f"(1.0f) : "memory");
        asm volatile("red.global.add.v2.f32 [%0], {%1, %2};"
                     :: "l"(&g_degcnt[cols.w]), "f"(w.w), "f"(1.0f) : "memory");
    }
}

// ---------------- kernel 3: scan (atomic base) + barrier + fill -----------
__global__ void __launch_bounds__(256) k_scanfill(const int* __restrict__ ei,
                                                  const float* __restrict__ ew) {
    __shared__ int s[256];
    __shared__ int sbase;
    int t = threadIdx.x, b = blockIdx.x;

    if (b < SCAN_BLOCKS) {
        int i = b * 256 + t;
        int c = 0;
        if (i < NN) {
            float2 dc = g_degcnt[i];
            g_dinv[i] = rsqrtf(dc.x);
            c = (int)dc.y;
        }
        s[t] = c;
        __syncthreads();
        for (int off = 1; off < 256; off <<= 1) {
            int u = (t >= off) ? s[t - off] : 0;
            __syncthreads();
            s[t] += u;
            __syncthreads();
        }
        if (t == 255) sbase = atomicAdd(&g_base, s[255]);
        __syncthreads();
        if (i < NN) {
            int ex = sbase + s[t] - c;
            g_start[i] = ex;
            g_cur[i] = ex;
        }
    }

    __threadfence();
    __syncthreads();
    if (t == 0) {
        atomicAdd((int*)&g_barrier, 1);
        while (g_barrier < SF_BLOCKS) { }
    }
    __syncthreads();
    __threadfence();

    int stride = SF_BLOCKS * 256 * 2;
    for (int e = (b * 256 + t) * 2; e < EE; e += stride) {
        int2 rows = *(const int2*)&ei[e];
        int2 cols = *(const int2*)&ei[EE + e];
        float2 w = *(const float2*)&ew[e];
        float c0 = g_dinv[rows.x] * w.x;
        float c1 = g_dinv[rows.y] * w.y;
        int p0 = atomicAdd(&g_cur[cols.x], 1);
        g_rec[p0] = make_int2(rows.x, __float_as_int(c0));
        int p1 = atomicAdd(&g_cur[cols.y], 1);
        g_rec[p1] = make_int2(rows.y, __float_as_int(c1));
    }
}

// ---------------- kernel 4: FUSED gather + collapsed GRU + BN stats -------
__global__ void __launch_bounds__(256) k_fused() {
    __shared__ float bsum[64], bsq[64];
    __shared__ __align__(16) float tw[8][96];    // per-warp transpose buffer
    if (threadIdx.x < 64) { bsum[threadIdx.x] = 0.f; bsq[threadIdx.x] = 0.f; }
    __syncthreads();

    int lane = threadIdx.x & 31;
    int warp = threadIdx.x >> 5;
    bool act = lane < 24;
    int grp = (lane >= 12 && lane < 24) ? 1 : 0;
    int sub = act ? (lane - grp * 12) : 0;

    // packed gate weights: az2[i] = (Az[i][2*lane], Az[i][2*lane+1])
    u64 az2[8], ah2[8];
    #pragma unroll
    for (int i = 0; i < 8; i++) {
        az2[i] = *(const u64*)&g_Az[i * 64 + 2 * lane];
        ah2[i] = *(const u64*)&g_Ah[i * 64 + 2 * lane];
    }
    u64 cz2 = *(const u64*)&g_cz[2 * lane];
    u64 ch2 = *(const u64*)&g_ch[2 * lane];

    float psx = 0.f, psy = 0.f, pqx = 0.f, pqy = 0.f;

    for (int n = blockIdx.x * 8 + warp; n < NN; n += FUSED_BLOCKS * 8) {
        float2 dc = g_degcnt[n];
        float dn = rsqrtf(dc.x);
        int cnt = (int)dc.y;
        int start = g_start[n];

        u64 acc0 = 0, acc1 = 0, acc2 = 0, acc3 = 0;
        if (lane < 12) {                         // self term: coeff dn (×dn later = dn^2)
            const ulonglong2* bp = g_xT32 + n * 24;
            ulonglong2 vA = bp[sub], vB = bp[12 + sub];
            u64 c2 = pk(dn, dn);
            acc0 = ffma2(vA.x, c2, acc0); acc1 = ffma2(vA.y, c2, acc1);
            acc2 = ffma2(vB.x, c2, acc2); acc3 = ffma2(vB.y, c2, acc3);
        }

        int e = start, end = start + cnt;
        for (; e + 8 <= end; e += 8) {
            if (act) {
                int2 r0 = g_rec[e + grp];
                int2 r1 = g_rec[e + 2 + grp];
                int2 r2 = g_rec[e + 4 + grp];
                int2 r3 = g_rec[e + 6 + grp];
                const ulonglong2* b0 = g_xT32 + r0.x * 24;
                const ulonglong2* b1 = g_xT32 + r1.x * 24;
                const ulonglong2* b2 = g_xT32 + r2.x * 24;
                const ulonglong2* b3 = g_xT32 + r3.x * 24;
                ulonglong2 vA0 = b0[sub], vB0 = b0[12 + sub];
                ulonglong2 vA1 = b1[sub], vB1 = b1[12 + sub];
                ulonglong2 vA2 = b2[sub], vB2 = b2[12 + sub];
                ulonglong2 vA3 = b3[sub], vB3 = b3[12 + sub];
                u64 c0 = pk(__int_as_float(r0.y), __int_as_float(r0.y));
                u64 c1 = pk(__int_as_float(r1.y), __int_as_float(r1.y));
                u64 c2 = pk(__int_as_float(r2.y), __int_as_float(r2.y));
                u64 c3 = pk(__int_as_float(r3.y), __int_as_float(r3.y));
                acc0 = ffma2(vA0.x, c0, acc0); acc1 = ffma2(vA0.y, c0, acc1);
                acc2 = ffma2(vB0.x, c0, acc2); acc3 = ffma2(vB0.y, c0, acc3);
                acc0 = ffma2(vA1.x, c1, acc0); acc1 = ffma2(vA1.y, c1, acc1);
                acc2 = ffma2(vB1.x, c1, acc2); acc3 = ffma2(vB1.y, c1, acc3);
                acc0 = ffma2(vA2.x, c2, acc0); acc1 = ffma2(vA2.y, c2, acc1);
                acc2 = ffma2(vB2.x, c2, acc2); acc3 = ffma2(vB2.y, c2, acc3);
                acc0 = ffma2(vA3.x, c3, acc0); acc1 = ffma2(vA3.y, c3, acc1);
                acc2 = ffma2(vB3.x, c3, acc2); acc3 = ffma2(vB3.y, c3, acc3);
            }
        }
        for (; e < end; e += 2) {
            if (act && e + grp < end) {
                int2 r0 = g_rec[e + grp];
                const ulonglong2* b0 = g_xT32 + r0.x * 24;
                ulonglong2 vA0 = b0[sub], vB0 = b0[12 + sub];
                u64 c0 = pk(__int_as_float(r0.y), __int_as_float(r0.y));
                acc0 = ffma2(vA0.x, c0, acc0); acc1 = ffma2(vA0.y, c0, acc1);
                acc2 = ffma2(vB0.x, c0, acc2); acc3 = ffma2(vB0.y, c0, acc3);
            }
        }
        // combine the two edge groups (lanes 0..11 += lanes 12..23), apply dinv[col]
        acc0 = fadd2(acc0, __shfl_down_sync(0xffffffffu, acc0, 12));
        acc1 = fadd2(acc1, __shfl_down_sync(0xffffffffu, acc1, 12));
        acc2 = fadd2(acc2, __shfl_down_sync(0xffffffffu, acc2, 12));
        acc3 = fadd2(acc3, __shfl_down_sync(0xffffffffu, acc3, 12));
        u64 d2 = pk(dn, dn);
        acc0 = fmul2(acc0, d2); acc1 = fmul2(acc1, d2);
        acc2 = fmul2(acc2, d2); acc3 = fmul2(acc3, d2);

        // transpose to per-warp smem: tw[warp][sub*8 + f]
        __syncwarp();
        if (lane < 12) {
            ulonglong2* dst = (ulonglong2*)&tw[warp][sub * 8];
            dst[0] = make_ulonglong2(acc0, acc1);
            dst[1] = make_ulonglong2(acc2, acc3);
        }
        __syncwarp();

        // collapsed GRU: lane owns hidden dims 2*lane, 2*lane+1
        float hx = 0.f, hy = 0.f;
        #pragma unroll
        for (int p = 0; p < PP; p++) {
            float4 uA = *(const float4*)&tw[warp][p * 8];
            float4 uB = *(const float4*)&tw[warp][p * 8 + 4];
            u64 a = cz2, b = ch2;       // a pre-halved for tanh/sigmoid trick
            u64 s0 = pk(uA.x, uA.x); a = ffma2(az2[0], s0, a); b = ffma2(ah2[0], s0, b);
            u64 s1 = pk(uA.y, uA.y); a = ffma2(az2[1], s1, a); b = ffma2(ah2[1], s1, b);
            u64 s2 = pk(uA.z, uA.z); a = ffma2(az2[2], s2, a); b = ffma2(ah2[2], s2, b);
            u64 s3 = pk(uA.w, uA.w); a = ffma2(az2[3], s3, a); b = ffma2(ah2[3], s3, b);
            u64 s4 = pk(uB.x, uB.x); a = ffma2(az2[4], s4, a); b = ffma2(ah2[4], s4, b);
            u64 s5 = pk(uB.y, uB.y); a = ffma2(az2[5], s5, a); b = ffma2(ah2[5], s5, b);
            u64 s6 = pk(uB.z, uB.z); a = ffma2(az2[6], s6, a); b = ffma2(ah2[6], s6, b);
            u64 s7 = pk(uB.w, uB.w); a = ffma2(az2[7], s7, a); b = ffma2(ah2[7], s7, b);
            float ax, ay, bx, by;
            upk(a, ax, ay); upk(b, bx, by);
            float zx = fmaf(-0.5f, tanha(ax), 0.5f);   // 1 - sigmoid(2*ax)
            float zy = fmaf(-0.5f, tanha(ay), 0.5f);
            float tx = tanha(bx);
            float ty = tanha(by);
            float pw = g_probs[p];
            hx = fmaf(pw * zx, tx, hx);
            hy = fmaf(pw * zy, ty, hy);
        }
        __syncwarp();
        hx = fmaxf(hx, 0.f);
        hy = fmaxf(hy, 0.f);
        *(float2*)&g_H[n * 64 + 2 * lane] = make_float2(hx, hy);
        psx += hx; pqx += hx * hx;
        psy += hy; pqy += hy * hy;
    }

    atomicAdd(&bsum[2 * lane],     psx);
    atomicAdd(&bsum[2 * lane + 1], psy);
    atomicAdd(&bsq[2 * lane],      pqx);
    atomicAdd(&bsq[2 * lane + 1],  pqy);
    __syncthreads();
    if (threadIdx.x < 64) {
        atomicAdd(&g_sums[threadIdx.x],  bsum[threadIdx.x]);
        atomicAdd(&g_sumsq[threadIdx.x], bsq[threadIdx.x]);
    }
}

// ---------------- kernel 5: BN-fold + out = relu(H) @ W_eff + b_eff -------
__global__ void __launch_bounds__(256) k_out(const float* __restrict__ gamma,
                                             const float* __restrict__ beta,
                                             float* __restrict__ out) {
    __shared__ float sW[64 * 96];
    __shared__ float sb[96];
    __shared__ float ss[64], st[64];
    int tid = threadIdx.x;
    if (tid < 64) {
        float mean = g_sums[tid] * (1.0f / (float)NN);
        float var  = g_sumsq[tid] * (1.0f / (float)NN) - mean * mean;
        float sc = gamma[tid] * rsqrtf(var + 1e-5f);
        ss[tid] = sc;
        st[tid] = beta[tid] - mean * sc;
    }
    __syncthreads();
    for (int idx = tid; idx < 64 * 96; idx += 256)
        sW[idx] = ss[idx / 96] * g_Wc[idx];
    if (tid < 96) {
        float s = g_bc[tid];
        for (int k = 0; k < 64; k++) s += st[k] * g_Wc[k * 96 + tid];
        sb[tid] = s;
    }
    __syncthreads();

    int lane = tid & 31;
    int warp = tid >> 5;
    for (int n = blockIdx.x * 8 + warp; n < NN; n += OUT_BLOCKS * 8) {
        float2 h2 = *(const float2*)&g_H[n * 64 + 2 * lane];
        float a0 = sb[lane], a1 = sb[lane + 32], a2 = sb[lane + 64];
        #pragma unroll
        for (int i = 0; i < 64; i++) {
            float hv = __shfl_sync(0xffffffffu, (i & 1) ? h2.y : h2.x, i >> 1);
            const float* wr = &sW[i * 96];
            a0 = fmaf(hv, wr[lane],      a0);
            a1 = fmaf(hv, wr[lane + 32], a1);
            a2 = fmaf(hv, wr[lane + 64], a2);
        }
        float* ob = out + n * 96;
        ob[lane] = a0; ob[lane + 32] = a1; ob[lane + 64] = a2;
    }
}

// ---------------- launch ---------------------------------------------------
extern "C" void kernel_launch(void* const* d_in, const int* in_sizes, int n_in,
                              void* d_out, int out_size) {
    const float* x      = (const float*)d_in[0];
    const int*   ei     = (const int*)  d_in[1];
    const float* ew     = (const float*)d_in[2];
    const float* att    = (const float*)d_in[3];
    const float* conv_w = (const float*)d_in[4];
    const float* conv_b = (const float*)d_in[5];
    const float* lin_w  = (const float*)d_in[6];
    const float* lin_b  = (const float*)d_in[7];
    const float* gamma  = (const float*)d_in[8];
    const float* beta   = (const float*)d_in[9];
    const float* W1 = (const float*)d_in[10]; const float* b1 = (const float*)d_in[11];
    const float* W2 = (const float*)d_in[12]; const float* b2 = (const float*)d_in[13];
    const float* W3 = (const float*)d_in[14]; const float* b3 = (const float*)d_in[15];
    const float* W4 = (const float*)d_in[16]; const float* b4 = (const float*)d_in[17];
    const float* W5 = (const float*)d_in[18]; const float* b5 = (const float*)d_in[19];
    float* out = (float*)d_out;

    k_pre0<<<PREPX_BLOCKS + 1, 256>>>(x, att, conv_w, conv_b, lin_w, lin_b,
                                      W1, b1, W2, b2, W3, b3, W4, b4, W5, b5);
    k_count<<<(EE / 4 + 255) / 256, 256>>>(ei, ew);
    k_scanfill<<<SF_BLOCKS, 256>>>(ei, ew);
    k_fused<<<FUSED_BLOCKS, 256>>>();
    k_out<<<OUT_BLOCKS, 256>>>(gamma, beta, out);
}

// round 7
// speedup vs baseline: 1.9104x; 1.0533x over previous
#include <cuda_runtime.h>

#define NN 50000
#define EE 800000
#define PP 12
#define SCAN_BLOCKS 196      // ceil(NN/256)
#define NTILES 1563          // ceil(NN/32)
#define GB 444               // 148 SMs * 3 blocks — co-resident persistent grid

typedef unsigned long long u64;

// ---------------- scratch (device globals; no allocation) ----------------
__device__ float2 g_degcnt[NN];          // .x = deg(+1 self), .y = in-edge count
__device__ float  g_dinv[NN];
__device__ int    g_start[NN];
__device__ int    g_cur[NN];
__device__ int    g_base;                // atomic CSR base allocator
__device__ unsigned g_count;             // grid barrier counter (monotonic per run)
__device__ int2   g_rec[EE];             // CSR-ordered {row, coeff = dinv[row]*ew}
__device__ ulonglong2 g_xT32[NN * 24];   // fp32 features: [n][h][sub] float4
__device__ float  g_H[NN * 64];          // relu(H_accum)
__device__ float  g_sums[64];
__device__ float  g_sumsq[64];
__device__ float  g_Az[8 * 64], g_Ah[8 * 64];   // Az, cz pre-folded by 0.5
__device__ float  g_cz[64], g_ch[64];
__device__ float  g_probs[PP];
__device__ float  g_Wc[64 * 96], g_bc[96];

__device__ __forceinline__ float tanha(float x) {
    float r; asm("tanh.approx.f32 %0, %1;" : "=f"(r) : "f"(x)); return r;
}
__device__ __forceinline__ u64 pk(float x, float y) {
    u64 r; asm("mov.b64 %0, {%1, %2};" : "=l"(r) : "f"(x), "f"(y)); return r;
}
__device__ __forceinline__ void upk(u64 v, float& x, float& y) {
    asm("mov.b64 {%0, %1}, %2;" : "=f"(x), "=f"(y) : "l"(v));
}
__device__ __forceinline__ u64 ffma2(u64 a, u64 b, u64 c) {
    u64 d; asm("fma.rn.f32x2 %0, %1, %2, %3;" : "=l"(d) : "l"(a), "l"(b), "l"(c)); return d;
}
__device__ __forceinline__ u64 fadd2(u64 a, u64 b) {
    u64 d; asm("add.rn.f32x2 %0, %1, %2;" : "=l"(d) : "l"(a), "l"(b)); return d;
}
__device__ __forceinline__ u64 fmul2(u64 a, u64 b) {
    u64 d; asm("mul.rn.f32x2 %0, %1, %2;" : "=l"(d) : "l"(a), "l"(b)); return d;
}

// monotonic-counter grid barrier; k = 1,2,3,... within one kernel run
__device__ __forceinline__ void gbar(int k) {
    __syncthreads();
    if (threadIdx.x == 0) {
        __threadfence();
        atomicAdd(&g_count, 1u);
        while (*(volatile unsigned*)&g_count < (unsigned)(GB * k)) __nanosleep(32);
        __threadfence();
    }
    __syncthreads();
}

// ---------------- kernel A: reset barrier/allocator ------------------------
__global__ void k_reset() {
    g_count = 0u;
    g_base = 0;
}

// ---------------- kernel B: the whole pipeline, one persistent grid --------
__global__ void __launch_bounds__(256, 3) k_mega(
        const float* __restrict__ x,
        const int*   __restrict__ ei,
        const float* __restrict__ ew,
        const float* __restrict__ att,
        const float* __restrict__ conv_w, const float* __restrict__ conv_b,
        const float* __restrict__ lin_w,  const float* __restrict__ lin_b,
        const float* __restrict__ gamma,  const float* __restrict__ beta,
        const float* __restrict__ W1, const float* __restrict__ b1,
        const float* __restrict__ W2, const float* __restrict__ b2,
        const float* __restrict__ W3, const float* __restrict__ b3,
        const float* __restrict__ W4, const float* __restrict__ b4,
        const float* __restrict__ W5, const float* __restrict__ b5,
        float* __restrict__ out) {
    __shared__ __align__(16) char smraw[25600];
    int tid = threadIdx.x, bid = blockIdx.x;

    // ================= P0: init degcnt + transpose x + fold weights ========
    {
        for (int i = bid * 256 + tid; i < NN; i += GB * 256)
            g_degcnt[i] = make_float2(1.0f, 0.0f);

        float* s = (float*)smraw;                 // 32*96 floats = 12KB
        for (int tile = bid; tile < NTILES; tile += GB) {
            int blockNode = tile * 32;
            int lim = (NN - blockNode) * 96;
            __syncthreads();
            for (int i = tid; i < 32 * 96; i += 256)
                s[i] = (i < lim) ? x[blockNode * 96 + i] : 0.f;
            __syncthreads();
            #pragma unroll
            for (int k = 0; k < 3; k++) {
                int o = tid + k * 256;            // 0..767 = 32 nodes * 24 float4
                int ln = o / 24, l = o - ln * 24;
                int n = blockNode + ln;
                if (n < NN) {
                    int h = l / 12, sub = l - h * 12;
                    float4 v;
                    v.x = s[ln * 96 + (h * 4 + 0) * 12 + sub];
                    v.y = s[ln * 96 + (h * 4 + 1) * 12 + sub];
                    v.z = s[ln * 96 + (h * 4 + 2) * 12 + sub];
                    v.w = s[ln * 96 + (h * 4 + 3) * 12 + sub];
                    *(float4*)&g_xT32[n * 24 + h * 12 + sub] = v;
                }
            }
        }

        if (bid == GB - 1) {
            // small linear-algebra folds (one block)
            __syncthreads();
            float* sT1 = (float*)smraw;           // 2048 floats
            float* sT2 = sT1 + 2048;              // 1024
            float* sT3 = sT2 + 1024;              // 512
            float* sbb = sT3 + 512;               // 56

            if (tid == 0) {
                float m = -1e30f;
                for (int i = 0; i < PP; i++) m = fmaxf(m, att[i]);
                float e[PP], ssum = 0.f;
                for (int i = 0; i < PP; i++) { e[i] = __expf(att[i] - m); ssum += e[i]; }
                for (int i = 0; i < PP; i++) g_probs[i] = e[i] / ssum;
            }
            for (int idx = tid; idx < 8 * 64; idx += 256) {
                int i = idx >> 6, j = idx & 63;
                float az = 0.f, ah = 0.f;
                for (int k = 0; k < 64; k++) {
                    az += conv_w[0 * 512 + i * 64 + k] * lin_w[0 * 8192 + k * 64 + j];
                    ah += conv_w[2 * 512 + i * 64 + k] * lin_w[2 * 8192 + k * 64 + j];
                }
                g_Az[idx] = 0.5f * az; g_Ah[idx] = ah;
            }
            for (int j = tid; j < 64; j += 256) {
                float cz = lin_b[0 * 64 + j], ch = lin_b[2 * 64 + j];
                for (int k = 0; k < 64; k++) {
                    cz += conv_b[0 * 64 + k] * lin_w[0 * 8192 + k * 64 + j];
                    ch += conv_b[2 * 64 + k] * lin_w[2 * 8192 + k * 64 + j];
                }
                g_cz[j] = 0.5f * cz; g_ch[j] = ch;
                g_sums[j] = 0.f; g_sumsq[j] = 0.f;
            }
            for (int idx = tid; idx < 64 * 32; idx += 256) {
                int i = idx >> 5, j = idx & 31; float s2 = 0.f;
                for (int k = 0; k < 64; k++) s2 += W1[i * 64 + k] * W2[k * 32 + j];
                sT1[idx] = s2;
            }
            if (tid < 32) { float s2 = b2[tid]; for (int k = 0; k < 64; k++) s2 += b1[k] * W2[k * 32 + tid]; sbb[tid] = s2; }
            __syncthreads();
            for (int idx = tid; idx < 64 * 16; idx += 256) {
                int i = idx >> 4, j = idx & 15; float s2 = 0.f;
                for (int k = 0; k < 32; k++) s2 += sT1[i * 32 + k] * W3[k * 16 + j];
                sT2[idx] = s2;
            }
            if (tid < 16) { float s2 = b3[tid]; for (int k = 0; k < 32; k++) s2 += sbb[k] * W3[k * 16 + tid]; sbb[32 + tid] = s2; }
            __syncthreads();
            for (int idx = tid; idx < 64 * 8; idx += 256) {
                int i = idx >> 3, j = idx & 7; float s2 = 0.f;
                for (int k = 0; k < 16; k++) s2 += sT2[i * 16 + k] * W4[k * 8 + j];
                sT3[idx] = s2;
            }
            if (tid < 8) { float s2 = b4[tid]; for (int k = 0; k < 16; k++) s2 += sbb[32 + k] * W4[k * 8 + tid]; sbb[48 + tid] = s2; }
            __syncthreads();
            for (int idx = tid; idx < 64 * 96; idx += 256) {
                int i = idx / 96, j = idx - i * 96; float s2 = 0.f;
                for (int k = 0; k < 8; k++) s2 += sT3[i * 8 + k] * W5[k * 96 + j];
                g_Wc[idx] = s2;
            }
            for (int j = tid; j < 96; j += 256) {
                float s2 = b5[j];
                for (int k = 0; k < 8; k++) s2 += sbb[48 + k] * W5[k * 96 + j];
                g_bc[j] = s2;
            }
        }
    }
    gbar(1);

    // ================= P1: degree + count (4 edges/thread) =================
    for (int e = (bid * 256 + tid) * 4; e < EE; e += GB * 256 * 4) {
        int4 cols = *(const int4*)&ei[EE + e];
        float4 w = *(const float4*)&ew[e];
        asm volatile("red.global.add.v2.f32 [%0], {%1, %2};"
                     :: "l"(&g_degcnt[cols.x]), "f"(w.x), "f"(1.0f) : "memory");
        asm volatile("red.global.add.v2.f32 [%0], {%1, %2};"
                     :: "l"(&g_degcnt[cols.y]), "f"(w.y), "f"(1.0f) : "memory");
        asm volatile("red.global.add.v2.f32 [%0], {%1, %2};"
                     :: "l"(&g_degcnt[cols.z]), "f"(w.z), "f"(1.0f) : "memory");
        asm volatile("red.global.add.v2.f32 [%0], {%1, %2};"
                     :: "l"(&g_degcnt[cols.w]), "f"(w.w), "f"(1.0f) : "memory");
    }
    gbar(2);

    // ================= P2: scan (atomic base) + dinv =======================
    if (bid < SCAN_BLOCKS) {
        int* s = (int*)smraw;                    // 256 ints
        int* sbase = s + 256;
        int i = bid * 256 + tid;
        int c = 0;
        if (i < NN) {
            float2 dc = g_degcnt[i];
            g_dinv[i] = rsqrtf(dc.x);
            c = (int)dc.y;
        }
        s[tid] = c;
        __syncthreads();
        for (int off = 1; off < 256; off <<= 1) {
            int u = (tid >= off) ? s[tid - off] : 0;
            __syncthreads();
            s[tid] += u;
            __syncthreads();
        }
        if (tid == 255) *sbase = atomicAdd(&g_base, s[255]);
        __syncthreads();
        if (i < NN) {
            int ex = *sbase + s[tid] - c;
            g_start[i] = ex;
            g_cur[i] = ex;
        }
    }
    gbar(3);

    // ================= P3: fill CSR records (2 edges/iter) =================
    for (int e = (bid * 256 + tid) * 2; e < EE; e += GB * 256 * 2) {
        int2 rows = *(const int2*)&ei[e];
        int2 cols = *(const int2*)&ei[EE + e];
        float2 w = *(const float2*)&ew[e];
        float c0 = g_dinv[rows.x] * w.x;
        float c1 = g_dinv[rows.y] * w.y;
        int p0 = atomicAdd(&g_cur[cols.x], 1);
        g_rec[p0] = make_int2(rows.x, __float_as_int(c0));
        int p1 = atomicAdd(&g_cur[cols.y], 1);
        g_rec[p1] = make_int2(rows.y, __float_as_int(c1));
    }
    gbar(4);

    // ================= P4: fused gather + GRU + BN stats ===================
    {
        float* bsum = (float*)smraw;             // 64
        float* bsq  = bsum + 64;                 // 64
        float* tw   = bsq + 64;                  // 8 warps * 96
        if (tid < 64) { bsum[tid] = 0.f; bsq[tid] = 0.f; }
        __syncthreads();

        int lane = tid & 31;
        int warp = tid >> 5;
        bool actv = lane < 24;
        int grp = (lane >= 12 && lane < 24) ? 1 : 0;
        int sub = actv ? (lane - grp * 12) : 0;
        float* twr = tw + warp * 96;

        u64 az2[8], ah2[8];
        #pragma unroll
        for (int i = 0; i < 8; i++) {
            az2[i] = *(const u64*)&g_Az[i * 64 + 2 * lane];
            ah2[i] = *(const u64*)&g_Ah[i * 64 + 2 * lane];
        }
        u64 cz2 = *(const u64*)&g_cz[2 * lane];
        u64 ch2 = *(const u64*)&g_ch[2 * lane];

        float psx = 0.f, psy = 0.f, pqx = 0.f, pqy = 0.f;

        for (int n = bid * 8 + warp; n < NN; n += GB * 8) {
            float2 dc = g_degcnt[n];
            float dn = rsqrtf(dc.x);
            int cnt = (int)dc.y;
            int start = g_start[n];

            u64 acc0 = 0, acc1 = 0, acc2 = 0, acc3 = 0;
            if (lane < 12) {
                const ulonglong2* bp = g_xT32 + n * 24;
                ulonglong2 vA = bp[sub], vB = bp[12 + sub];
                u64 c2 = pk(dn, dn);
                acc0 = ffma2(vA.x, c2, acc0); acc1 = ffma2(vA.y, c2, acc1);
                acc2 = ffma2(vB.x, c2, acc2); acc3 = ffma2(vB.y, c2, acc3);
            }

            int e = start, end = start + cnt;
            for (; e + 8 <= end; e += 8) {
                if (actv) {
                    int2 r0 = g_rec[e + grp];
                    int2 r1 = g_rec[e + 2 + grp];
                    int2 r2 = g_rec[e + 4 + grp];
                    int2 r3 = g_rec[e + 6 + grp];
                    const ulonglong2* b0 = g_xT32 + r0.x * 24;
                    const ulonglong2* b1 = g_xT32 + r1.x * 24;
                    const ulonglong2* b2 = g_xT32 + r2.x * 24;
                    const ulonglong2* b3 = g_xT32 + r3.x * 24;
                    ulonglong2 vA0 = b0[sub], vB0 = b0[12 + sub];
                    ulonglong2 vA1 = b1[sub], vB1 = b1[12 + sub];
                    ulonglong2 vA2 = b2[sub], vB2 = b2[12 + sub];
                    ulonglong2 vA3 = b3[sub], vB3 = b3[12 + sub];
                    u64 c0 = pk(__int_as_float(r0.y), __int_as_float(r0.y));
                    u64 c1 = pk(__int_as_float(r1.y), __int_as_float(r1.y));
                    u64 c2 = pk(__int_as_float(r2.y), __int_as_float(r2.y));
                    u64 c3 = pk(__int_as_float(r3.y), __int_as_float(r3.y));
                    acc0 = ffma2(vA0.x, c0, acc0); acc1 = ffma2(vA0.y, c0, acc1);
                    acc2 = ffma2(vB0.x, c0, acc2); acc3 = ffma2(vB0.y, c0, acc3);
                    acc0 = ffma2(vA1.x, c1, acc0); acc1 = ffma2(vA1.y, c1, acc1);
                    acc2 = ffma2(vB1.x, c1, acc2); acc3 = ffma2(vB1.y, c1, acc3);
                    acc0 = ffma2(vA2.x, c2, acc0); acc1 = ffma2(vA2.y, c2, acc1);
                    acc2 = ffma2(vB2.x, c2, acc2); acc3 = ffma2(vB2.y, c2, acc3);
                    acc0 = ffma2(vA3.x, c3, acc0); acc1 = ffma2(vA3.y, c3, acc1);
                    acc2 = ffma2(vB3.x, c3, acc2); acc3 = ffma2(vB3.y, c3, acc3);
                }
            }
            for (; e < end; e += 2) {
                if (actv && e + grp < end) {
                    int2 r0 = g_rec[e + grp];
                    const ulonglong2* b0 = g_xT32 + r0.x * 24;
                    ulonglong2 vA0 = b0[sub], vB0 = b0[12 + sub];
                    u64 c0 = pk(__int_as_float(r0.y), __int_as_float(r0.y));
                    acc0 = ffma2(vA0.x, c0, acc0); acc1 = ffma2(vA0.y, c0, acc1);
                    acc2 = ffma2(vB0.x, c0, acc2); acc3 = ffma2(vB0.y, c0, acc3);
                }
            }
            acc0 = fadd2(acc0, __shfl_down_sync(0xffffffffu, acc0, 12));
            acc1 = fadd2(acc1, __shfl_down_sync(0xffffffffu, acc1, 12));
            acc2 = fadd2(acc2, __shfl_down_sync(0xffffffffu, acc2, 12));
            acc3 = fadd2(acc3, __shfl_down_sync(0xffffffffu, acc3, 12));
            u64 d2 = pk(dn, dn);
            acc0 = fmul2(acc0, d2); acc1 = fmul2(acc1, d2);
            acc2 = fmul2(acc2, d2); acc3 = fmul2(acc3, d2);

            __syncwarp();
            if (lane < 12) {
                ulonglong2* dst = (ulonglong2*)&twr[sub * 8];
                dst[0] = make_ulonglong2(acc0, acc1);
                dst[1] = make_ulonglong2(acc2, acc3);
            }
            __syncwarp();

            float hx = 0.f, hy = 0.f;
            #pragma unroll
            for (int p = 0; p < PP; p++) {
                float4 uA = *(const float4*)&twr[p * 8];
                float4 uB = *(const float4*)&twr[p * 8 + 4];
                u64 a = cz2, b = ch2;
                u64 s0 = pk(uA.x, uA.x); a = ffma2(az2[0], s0, a); b = ffma2(ah2[0], s0, b);
                u64 s1 = pk(uA.y, uA.y); a = ffma2(az2[1], s1, a); b = ffma2(ah2[1], s1, b);
                u64 s2 = pk(uA.z, uA.z); a = ffma2(az2[2], s2, a); b = ffma2(ah2[2], s2, b);
                u64 s3 = pk(uA.w, uA.w); a = ffma2(az2[3], s3, a); b = ffma2(ah2[3], s3, b);
                u64 s4 = pk(uB.x, uB.x); a = ffma2(az2[4], s4, a); b = ffma2(ah2[4], s4, b);
                u64 s5 = pk(uB.y, uB.y); a = ffma2(az2[5], s5, a); b = ffma2(ah2[5], s5, b);
                u64 s6 = pk(uB.z, uB.z); a = ffma2(az2[6], s6, a); b = ffma2(ah2[6], s6, b);
                u64 s7 = pk(uB.w, uB.w); a = ffma2(az2[7], s7, a); b = ffma2(ah2[7], s7, b);
                float ax, ay, bx, by;
                upk(a, ax, ay); upk(b, bx, by);
                float zx = fmaf(-0.5f, tanha(ax), 0.5f);
                float zy = fmaf(-0.5f, tanha(ay), 0.5f);
                float tx = tanha(bx);
                float ty = tanha(by);
                float pw = g_probs[p];
                hx = fmaf(pw * zx, tx, hx);
                hy = fmaf(pw * zy, ty, hy);
            }
            __syncwarp();
            hx = fmaxf(hx, 0.f);
            hy = fmaxf(hy, 0.f);
            *(float2*)&g_H[n * 64 + 2 * lane] = make_float2(hx, hy);
            psx += hx; pqx += hx * hx;
            psy += hy; pqy += hy * hy;
        }

        atomicAdd(&bsum[2 * lane],     psx);
        atomicAdd(&bsum[2 * lane + 1], psy);
        atomicAdd(&bsq[2 * lane],      pqx);
        atomicAdd(&bsq[2 * lane + 1],  pqy);
        __syncthreads();
        if (tid < 64) {
            atomicAdd(&g_sums[tid],  bsum[tid]);
            atomicAdd(&g_sumsq[tid], bsq[tid]);
        }
    }
    gbar(5);

    // ================= P5: BN-fold + out = relu(H) @ W_eff + b_eff =========
    {
        float* sW = (float*)smraw;               // 64*96
        float* sb = sW + 64 * 96;                // 96
        float* ss = sb + 96;                     // 64
        float* st = ss + 64;                     // 64
        if (tid < 64) {
            float mean = g_sums[tid] * (1.0f / (float)NN);
            float var  = g_sumsq[tid] * (1.0f / (float)NN) - mean * mean;
            float sc = gamma[tid] * rsqrtf(var + 1e-5f);
            ss[tid] = sc;
            st[tid] = beta[tid] - mean * sc;
        }
        __syncthreads();
        for (int idx = tid; idx < 64 * 96; idx += 256)
            sW[idx] = ss[idx / 96] * g_Wc[idx];
        if (tid < 96) {
            float s2 = g_bc[tid];
            for (int k = 0; k < 64; k++) s2 += st[k] * g_Wc[k * 96 + tid];
            sb[tid] = s2;
        }
        __syncthreads();

        int lane = tid & 31;
        int warp = tid >> 5;
        for (int n = bid * 8 + warp; n < NN; n += GB * 8) {
            float2 h2 = *(const float2*)&g_H[n * 64 + 2 * lane];
            float a0 = sb[lane], a1 = sb[lane + 32], a2 = sb[lane + 64];
            #pragma unroll
            for (int i = 0; i < 64; i++) {
                float hv = __shfl_sync(0xffffffffu, (i & 1) ? h2.y : h2.x, i >> 1);
                const float* wr = &sW[i * 96];
                a0 = fmaf(hv, wr[lane],      a0);
                a1 = fmaf(hv, wr[lane + 32], a1);
                a2 = fmaf(hv, wr[lane + 64], a2);
            }
            float* ob = out + n * 96;
            ob[lane] = a0; ob[lane + 32] = a1; ob[lane + 64] = a2;
        }
    }
}

// ---------------- launch ---------------------------------------------------
extern "C" void kernel_launch(void* const* d_in, const int* in_sizes, int n_in,
                              void* d_out, int out_size) {
    const float* x      = (const float*)d_in[0];
    const int*   ei     = (const int*)  d_in[1];
    const float* ew     = (const float*)d_in[2];
    const float* att    = (const float*)d_in[3];
    const float* conv_w = (const float*)d_in[4];
    const float* conv_b = (const float*)d_in[5];
    const float* lin_w  = (const float*)d_in[6];
    const float* lin_b  = (const float*)d_in[7];
    const float* gamma  = (const float*)d_in[8];
    const float* beta   = (const float*)d_in[9];
    const float* W1 = (const float*)d_in[10]; const float* b1 = (const float*)d_in[11];
    const float* W2 = (const float*)d_in[12]; const float* b2 = (const float*)d_in[13];
    const float* W3 = (const float*)d_in[14]; const float* b3 = (const float*)d_in[15];
    const float* W4 = (const float*)d_in[16]; const float* b4 = (const float*)d_in[17];
    const float* W5 = (const float*)d_in[18]; const float* b5 = (const float*)d_in[19];
    float* out = (float*)d_out;

    k_reset<<<1, 1>>>();
    k_mega<<<GB, 256>>>(x, ei, ew, att, conv_w, conv_b, lin_w, lin_b,
                        gamma, beta, W1, b1, W2, b2, W3, b3, W4, b4, W5, b5, out);
}